// round 1
// baseline (speedup 1.0000x reference)
#include <cuda_runtime.h>
#include <cuda_bf16.h>
#include <stdint.h>

// Problem constants (B, D, F, target_l0) — fixed by the dataset.
#define NB 1024
#define ND 1024
#define NF 32768
#define L0 32
#define EPSF 1e-3f

// ---------------- device state (no allocations allowed) ----------------
__device__ float              g_res[NB * ND];       // residual [B,D]
__device__ float              g_w[NB * L0];         // sparse weights
__device__ int                g_idx[NB * L0];       // sparse indices
__device__ int                g_cnt[NB];            // active count per row
__device__ unsigned long long g_key[NB];            // argmax packed keys

// pack (value, index) so that larger key == (larger value, then smaller index)
__device__ __forceinline__ unsigned long long pack_key(float v, int idx) {
    unsigned u = __float_as_uint(v);
    u = (u & 0x80000000u) ? ~u : (u | 0x80000000u);
    return ((unsigned long long)u << 32) | (unsigned)(0xFFFFFFFFu - (unsigned)idx);
}

// ---------------- K0: init ----------------
__global__ void k_init(const float* __restrict__ x) {
    int i = blockIdx.x * blockDim.x + threadIdx.x;
    if (i < NB * ND) g_res[i] = x[i];
    if (i < NB) { g_cnt[i] = 0; g_key[i] = 0ull; }
}

// ---------------- K2: fused SGEMM (residual @ xs^T) + per-row argmax ----------------
// C[b][f] = sum_d res[b][d] * xs[f][d];  both operands K-contiguous (NT gemm).
#define BM 64
#define BN 128
#define BK 16
#define TM 4
#define TN 8
// 256 threads: 16 (n) x 16 (m)

__global__ __launch_bounds__(256) void k_gemm_argmax(const float* __restrict__ xs) {
    __shared__ float As[BK][BM + 4];
    __shared__ float Bs[BK][BN + 4];
    __shared__ unsigned long long red[BM][16];

    const int bx = blockIdx.x;           // F tile
    const int by = blockIdx.y;           // B tile
    const int tid = threadIdx.x;
    const int tx = tid & 15;             // n dir
    const int ty = tid >> 4;             // m dir
    const int row0 = by * BM;
    const int col0 = bx * BN;

    float acc[TM][TN];
#pragma unroll
    for (int i = 0; i < TM; i++)
#pragma unroll
        for (int j = 0; j < TN; j++) acc[i][j] = 0.f;

    const int a_r  = tid >> 2;           // 0..63
    const int a_c4 = tid & 3;            // which float4 of 16 k's
    const float* Ag = g_res + (size_t)row0 * ND;
    const float* Bg = xs    + (size_t)col0 * ND;

    for (int k0 = 0; k0 < ND; k0 += BK) {
        // load A tile (64x16), one float4/thread, store transposed
        float4 av = *(const float4*)(Ag + (size_t)a_r * ND + k0 + a_c4 * 4);
        As[a_c4 * 4 + 0][a_r] = av.x;
        As[a_c4 * 4 + 1][a_r] = av.y;
        As[a_c4 * 4 + 2][a_r] = av.z;
        As[a_c4 * 4 + 3][a_r] = av.w;
        // load B tile (128x16), two float4/thread
#pragma unroll
        for (int h = 0; h < 2; h++) {
            float4 bv = *(const float4*)(Bg + (size_t)(a_r + 64 * h) * ND + k0 + a_c4 * 4);
            Bs[a_c4 * 4 + 0][a_r + 64 * h] = bv.x;
            Bs[a_c4 * 4 + 1][a_r + 64 * h] = bv.y;
            Bs[a_c4 * 4 + 2][a_r + 64 * h] = bv.z;
            Bs[a_c4 * 4 + 3][a_r + 64 * h] = bv.w;
        }
        __syncthreads();
#pragma unroll
        for (int k = 0; k < BK; k++) {
            float ar[TM], br[TN];
#pragma unroll
            for (int i = 0; i < TM; i++) ar[i] = As[k][ty * TM + i];
#pragma unroll
            for (int j = 0; j < TN; j++) br[j] = Bs[k][tx * TN + j];
#pragma unroll
            for (int i = 0; i < TM; i++)
#pragma unroll
                for (int j = 0; j < TN; j++)
                    acc[i][j] = fmaf(ar[i], br[j], acc[i][j]);
        }
        __syncthreads();
    }

    // per-thread best per row, then cross-tx reduce, then global atomic merge
    const int base_col = col0 + tx * TN;
#pragma unroll
    for (int i = 0; i < TM; i++) {
        unsigned long long best = 0ull;
#pragma unroll
        for (int j = 0; j < TN; j++) {
            unsigned long long kk = pack_key(acc[i][j], base_col + j);
            if (kk > best) best = kk;
        }
        red[ty * TM + i][tx] = best;
    }
    __syncthreads();
    if (tid < BM) {
        unsigned long long best = 0ull;
#pragma unroll
        for (int t = 0; t < 16; t++)
            if (red[tid][t] > best) best = red[tid][t];
        atomicMax(&g_key[row0 + tid], best);
    }
}

// ---------------- K3: per-row update (append argmax, grads, step, relu, compact,
//                      rebuild residual), one block of 128 threads per row ----------------
__global__ __launch_bounds__(128) void k_update(const float* __restrict__ x,
                                                const float* __restrict__ xs) {
    const int b = blockIdx.x;
    const int tid = threadIdx.x;
    const int warp = tid >> 5, lane = tid & 31;

    __shared__ int   s_idx[L0];
    __shared__ float s_w[L0];
    __shared__ float s_g[L0];
    __shared__ int   s_cnt;
    __shared__ float s_step;
    __shared__ float w_cc[4], w_cr[4];

    if (tid == 0) {
        int cnt = g_cnt[b];
        for (int j = 0; j < cnt; j++) { s_idx[j] = g_idx[b * L0 + j]; s_w[j] = g_w[b * L0 + j]; }
        unsigned long long key = g_key[b];
        int f = (int)(0xFFFFFFFFu - (unsigned)(key & 0xFFFFFFFFull));
        bool present = false;
        for (int j = 0; j < cnt; j++) if (s_idx[j] == f) { present = true; break; }
        if (!present) { s_idx[cnt] = f; s_w[cnt] = 0.f; cnt++; }
        s_cnt = cnt;
        g_key[b] = 0ull;   // reset for next iteration
    }
    __syncthreads();
    const int m = s_cnt;
    const float* r = g_res + (size_t)b * ND;

    // g_j = <r, xs[idx_j]>, one warp per j (round-robin)
    for (int j = warp; j < m; j += 4) {
        const float* a = xs + (size_t)s_idx[j] * ND;
        float s = 0.f;
        for (int d = lane; d < ND; d += 32) s = fmaf(r[d], a[d], s);
#pragma unroll
        for (int o = 16; o; o >>= 1) s += __shfl_xor_sync(0xffffffffu, s, o);
        if (lane == 0) s_g[j] = s;
    }
    __syncthreads();

    // c[d] = sum_j g_j xs[idx_j][d];  cc = <c,c>;  cr = <c,r>
    float cc = 0.f, cr = 0.f;
    for (int d = tid; d < ND; d += 128) {
        float c = 0.f;
        for (int j = 0; j < m; j++) c = fmaf(s_g[j], xs[(size_t)s_idx[j] * ND + d], c);
        cc = fmaf(c, c, cc);
        cr = fmaf(c, r[d], cr);
    }
#pragma unroll
    for (int o = 16; o; o >>= 1) {
        cc += __shfl_xor_sync(0xffffffffu, cc, o);
        cr += __shfl_xor_sync(0xffffffffu, cr, o);
    }
    if (lane == 0) { w_cc[warp] = cc; w_cr[warp] = cr; }
    __syncthreads();
    if (tid == 0) {
        float tcc = 0.f, tcr = 0.f;
        for (int wv = 0; wv < 4; wv++) { tcc += w_cc[wv]; tcr += w_cr[wv]; }
        s_step = tcr / fmaxf(tcc, EPSF);
    }
    __syncthreads();
    const float step = s_step;

    // relu update + compaction (serial on thread 0; m <= 32)
    if (tid == 0) {
        int nc = 0;
        for (int j = 0; j < m; j++) {
            float wn = fmaxf(s_w[j] + step * s_g[j], 0.f);
            if (wn > 0.f) { s_idx[nc] = s_idx[j]; s_w[nc] = wn; nc++; }
        }
        s_cnt = nc;
        g_cnt[b] = nc;
        for (int j = 0; j < nc; j++) { g_idx[b * L0 + j] = s_idx[j]; g_w[b * L0 + j] = s_w[j]; }
    }
    __syncthreads();
    const int nc = s_cnt;

    // rebuild residual for next iteration: r = x - sum_j w_j xs[idx_j]
    for (int d = tid; d < ND; d += 128) {
        float v = x[(size_t)b * ND + d];
        for (int j = 0; j < nc; j++) v = fmaf(-s_w[j], xs[(size_t)s_idx[j] * ND + d], v);
        g_res[(size_t)b * ND + d] = v;
    }
}

// ---------------- K4: top_k emulation + decode + losses ----------------
__global__ __launch_bounds__(256) void k_finalize(const float* __restrict__ y,
                                                  const float* __restrict__ xs,
                                                  const float* __restrict__ ys,
                                                  float* __restrict__ out) {
    const int b = blockIdx.x;
    const int tid = threadIdx.x;

    __shared__ int   s_idx[L0];
    __shared__ float s_w[L0];
    __shared__ int   s_m;
    __shared__ float wred[8];

    if (tid == 0) {
        int   ti[L0]; float tw[L0];
        int m = g_cnt[b];
        for (int j = 0; j < m; j++) { ti[j] = g_idx[b * L0 + j]; tw[j] = g_w[b * L0 + j]; }
        // stable sort: value desc, index asc on ties (matches jax.lax.top_k)
        for (int i = 1; i < m; i++) {
            float wv = tw[i]; int iv = ti[i]; int j = i - 1;
            while (j >= 0 && (tw[j] < wv || (tw[j] == wv && ti[j] > iv))) {
                tw[j + 1] = tw[j]; ti[j + 1] = ti[j]; j--;
            }
            tw[j + 1] = wv; ti[j + 1] = iv;
        }
        // zero-pad with smallest indices whose weight is zero (top_k tie rule)
        int k = m, f = 0;
        while (k < L0) {
            bool used = false;
            for (int j = 0; j < m; j++) if (ti[j] == f) { used = true; break; }
            if (!used) { ti[k] = f; tw[k] = 0.f; k++; }
            f++;
        }
        for (int j = 0; j < L0; j++) { s_idx[j] = ti[j]; s_w[j] = tw[j]; }
        s_m = m;
    }
    __syncthreads();

    float* out_w = out;                                 // [B,L0]
    float* out_i = out + (size_t)NB * L0;               // [B,L0] (indices as float)
    float* out_x = out + (size_t)2 * NB * L0;           // [B,D]
    float* out_y = out_x + (size_t)NB * ND;             // [B,D]
    float* out_l = out_y + (size_t)NB * ND;             // [B]

    if (tid < L0) {
        out_w[b * L0 + tid] = s_w[tid];
        out_i[b * L0 + tid] = (float)s_idx[tid];
    }

    const int m = s_m;
    float lsum = 0.f;
    for (int d = tid; d < ND; d += 256) {
        float vx = 0.f, vy = 0.f;
        for (int j = 0; j < m; j++) {
            const float w = s_w[j];
            const size_t f = (size_t)s_idx[j];
            vx = fmaf(w, xs[f * ND + d], vx);
            vy = fmaf(w, ys[f * ND + d], vy);
        }
        out_x[(size_t)b * ND + d] = vx;
        out_y[(size_t)b * ND + d] = vy;
        const float e = vy - y[(size_t)b * ND + d];
        lsum = fmaf(e, e, lsum);
    }
#pragma unroll
    for (int o = 16; o; o >>= 1) lsum += __shfl_xor_sync(0xffffffffu, lsum, o);
    if ((tid & 31) == 0) wred[tid >> 5] = lsum;
    __syncthreads();
    if (tid == 0) {
        float t = 0.f;
        for (int i = 0; i < 8; i++) t += wred[i];
        out_l[b] = t;
    }
}

// ---------------- host launcher ----------------
extern "C" void kernel_launch(void* const* d_in, const int* in_sizes, int n_in,
                              void* d_out, int out_size) {
    // Map inputs robustly by size: first two of B*D elems -> x,y; first two of F*D -> xs,ys.
    const float* x = nullptr; const float* y = nullptr;
    const float* xs = nullptr; const float* ys = nullptr;
    for (int i = 0; i < n_in; i++) {
        if (in_sizes[i] == NB * ND) { if (!x) x = (const float*)d_in[i]; else if (!y) y = (const float*)d_in[i]; }
        else if (in_sizes[i] == NF * ND) { if (!xs) xs = (const float*)d_in[i]; else if (!ys) ys = (const float*)d_in[i]; }
    }
    float* out = (float*)d_out;

    k_init<<<(NB * ND + 255) / 256, 256>>>(x);
    dim3 gg(NF / BN, NB / BM);   // (256, 16)
    for (int t = 0; t < L0; t++) {
        k_gemm_argmax<<<gg, 256>>>(xs);
        k_update<<<NB, 128>>>(x, xs);
    }
    k_finalize<<<NB, 256>>>(y, xs, ys, out);
}

// round 2
// speedup vs baseline: 1.6524x; 1.6524x over previous
#include <cuda_runtime.h>
#include <cuda_bf16.h>
#include <stdint.h>

// Problem constants (B, D, F, target_l0) — fixed by the dataset.
#define NB 1024
#define ND 1024
#define NF 32768
#define L0 32
#define EPSF 1e-3f

// ---------------- device state (no allocations allowed) ----------------
__device__ float              g_res[NB * ND];       // residual [B,D]
__device__ float              g_w[NB * L0];         // sparse weights
__device__ int                g_idx[NB * L0];       // sparse indices
__device__ int                g_cnt[NB];            // active count per row
__device__ unsigned long long g_key[NB];            // argmax packed keys

// pack (value, index) so that larger key == (larger value, then smaller index)
__device__ __forceinline__ unsigned long long pack_key(float v, int idx) {
    unsigned u = __float_as_uint(v);
    u = (u & 0x80000000u) ? ~u : (u | 0x80000000u);
    return ((unsigned long long)u << 32) | (unsigned)(0xFFFFFFFFu - (unsigned)idx);
}

// ---------------- K0: init ----------------
__global__ void k_init(const float* __restrict__ x) {
    int i = blockIdx.x * blockDim.x + threadIdx.x;
    if (i < NB * ND) g_res[i] = x[i];
    if (i < NB) { g_cnt[i] = 0; g_key[i] = 0ull; }
}

// ---------------- K2: fused SGEMM (residual @ xs^T) + per-row argmax ----------------
// C[b][f] = sum_d res[b][d] * xs[f][d];  both operands K-contiguous (NT gemm).
// 128x128 block tile, 8x8 register tile, BK=16, double-buffered smem.
#define BM 128
#define BN 128
#define BK 16
#define NTHREADS 256

__global__ __launch_bounds__(NTHREADS, 2) void k_gemm_argmax(const float* __restrict__ xs) {
    __shared__ float As[2][BK][BM + 4];
    __shared__ float Bs[2][BK][BN + 4];

    // supertile swizzle: 128 blocks = 8 (by) x 16 (bx) share tiles in L2
    const int id = blockIdx.x;
    const int sup = id >> 7;               // 0..15
    const int wit = id & 127;
    const int by  = wit & 7;               // 0..7
    const int bx  = (sup << 4) + (wit >> 3);  // 0..255

    const int tid = threadIdx.x;
    const int tx = tid & 15;               // n dir
    const int ty = tid >> 4;               // m dir
    const int row0 = by * BM;
    const int col0 = bx * BN;

    const int r  = tid >> 2;               // 0..63
    const int c4 = tid & 3;                // which float4 of the 16 k's
    const float* Ag = g_res + (size_t)(row0 + r) * ND + c4 * 4;
    const float* Bg = xs    + (size_t)(col0 + r) * ND + c4 * 4;

    float acc[8][8];
#pragma unroll
    for (int i = 0; i < 8; i++)
#pragma unroll
        for (int j = 0; j < 8; j++) acc[i][j] = 0.f;

    // ---- initial stage load into buffer 0 ----
    {
        float4 a0 = *(const float4*)(Ag);
        float4 a1 = *(const float4*)(Ag + (size_t)64 * ND);
        float4 b0 = *(const float4*)(Bg);
        float4 b1 = *(const float4*)(Bg + (size_t)64 * ND);
        As[0][c4 * 4 + 0][r] = a0.x; As[0][c4 * 4 + 1][r] = a0.y;
        As[0][c4 * 4 + 2][r] = a0.z; As[0][c4 * 4 + 3][r] = a0.w;
        As[0][c4 * 4 + 0][r + 64] = a1.x; As[0][c4 * 4 + 1][r + 64] = a1.y;
        As[0][c4 * 4 + 2][r + 64] = a1.z; As[0][c4 * 4 + 3][r + 64] = a1.w;
        Bs[0][c4 * 4 + 0][r] = b0.x; Bs[0][c4 * 4 + 1][r] = b0.y;
        Bs[0][c4 * 4 + 2][r] = b0.z; Bs[0][c4 * 4 + 3][r] = b0.w;
        Bs[0][c4 * 4 + 0][r + 64] = b1.x; Bs[0][c4 * 4 + 1][r + 64] = b1.y;
        Bs[0][c4 * 4 + 2][r + 64] = b1.z; Bs[0][c4 * 4 + 3][r + 64] = b1.w;
    }
    __syncthreads();

    int buf = 0;
    for (int k0 = 0; k0 < ND; k0 += BK) {
        const bool has_next = (k0 + BK) < ND;
        float4 pa0, pa1, pb0, pb1;
        if (has_next) {
            pa0 = *(const float4*)(Ag + k0 + BK);
            pa1 = *(const float4*)(Ag + (size_t)64 * ND + k0 + BK);
            pb0 = *(const float4*)(Bg + k0 + BK);
            pb1 = *(const float4*)(Bg + (size_t)64 * ND + k0 + BK);
        }

#pragma unroll
        for (int k = 0; k < BK; k++) {
            float4 a0 = *(const float4*)&As[buf][k][ty * 8];
            float4 a1 = *(const float4*)&As[buf][k][ty * 8 + 4];
            float4 b0 = *(const float4*)&Bs[buf][k][tx * 8];
            float4 b1 = *(const float4*)&Bs[buf][k][tx * 8 + 4];
            const float ar[8] = {a0.x, a0.y, a0.z, a0.w, a1.x, a1.y, a1.z, a1.w};
            const float br[8] = {b0.x, b0.y, b0.z, b0.w, b1.x, b1.y, b1.z, b1.w};
#pragma unroll
            for (int i = 0; i < 8; i++)
#pragma unroll
                for (int j = 0; j < 8; j++)
                    acc[i][j] = fmaf(ar[i], br[j], acc[i][j]);
        }

        if (has_next) {
            const int nb = buf ^ 1;
            As[nb][c4 * 4 + 0][r] = pa0.x; As[nb][c4 * 4 + 1][r] = pa0.y;
            As[nb][c4 * 4 + 2][r] = pa0.z; As[nb][c4 * 4 + 3][r] = pa0.w;
            As[nb][c4 * 4 + 0][r + 64] = pa1.x; As[nb][c4 * 4 + 1][r + 64] = pa1.y;
            As[nb][c4 * 4 + 2][r + 64] = pa1.z; As[nb][c4 * 4 + 3][r + 64] = pa1.w;
            Bs[nb][c4 * 4 + 0][r] = pb0.x; Bs[nb][c4 * 4 + 1][r] = pb0.y;
            Bs[nb][c4 * 4 + 2][r] = pb0.z; Bs[nb][c4 * 4 + 3][r] = pb0.w;
            Bs[nb][c4 * 4 + 0][r + 64] = pb1.x; Bs[nb][c4 * 4 + 1][r + 64] = pb1.y;
            Bs[nb][c4 * 4 + 2][r + 64] = pb1.z; Bs[nb][c4 * 4 + 3][r + 64] = pb1.w;
            __syncthreads();
            buf = nb;
        }
    }

    // ---- epilogue: per-row argmax, reduced across the 16 tx lanes by shuffle ----
    const int base_col = col0 + tx * 8;
#pragma unroll
    for (int i = 0; i < 8; i++) {
        unsigned long long best = 0ull;
#pragma unroll
        for (int j = 0; j < 8; j++) {
            unsigned long long kk = pack_key(acc[i][j], base_col + j);
            if (kk > best) best = kk;
        }
        // lanes within a warp: lane = (ty&1)*16 + tx; xor over tx bits only
#pragma unroll
        for (int o = 1; o < 16; o <<= 1) {
            unsigned long long other = __shfl_xor_sync(0xffffffffu, best, o);
            if (other > best) best = other;
        }
        if (tx == 0)
            atomicMax(&g_key[row0 + ty * 8 + i], best);
    }
}

// ---------------- K3: per-row update (append argmax, grads, step, relu, compact,
//                      rebuild residual), one block of 128 threads per row ----------------
__global__ __launch_bounds__(128) void k_update(const float* __restrict__ x,
                                                const float* __restrict__ xs) {
    const int b = blockIdx.x;
    const int tid = threadIdx.x;
    const int warp = tid >> 5, lane = tid & 31;

    __shared__ int   s_idx[L0];
    __shared__ float s_w[L0];
    __shared__ float s_g[L0];
    __shared__ int   s_cnt;
    __shared__ float s_step;
    __shared__ float w_cc[4], w_cr[4];

    if (tid == 0) {
        int cnt = g_cnt[b];
        for (int j = 0; j < cnt; j++) { s_idx[j] = g_idx[b * L0 + j]; s_w[j] = g_w[b * L0 + j]; }
        unsigned long long key = g_key[b];
        int f = (int)(0xFFFFFFFFu - (unsigned)(key & 0xFFFFFFFFull));
        bool present = false;
        for (int j = 0; j < cnt; j++) if (s_idx[j] == f) { present = true; break; }
        if (!present) { s_idx[cnt] = f; s_w[cnt] = 0.f; cnt++; }
        s_cnt = cnt;
        g_key[b] = 0ull;   // reset for next iteration
    }
    __syncthreads();
    const int m = s_cnt;
    const float* r = g_res + (size_t)b * ND;

    // g_j = <r, xs[idx_j]>, one warp per j (round-robin)
    for (int j = warp; j < m; j += 4) {
        const float* a = xs + (size_t)s_idx[j] * ND;
        float s = 0.f;
        for (int d = lane; d < ND; d += 32) s = fmaf(r[d], a[d], s);
#pragma unroll
        for (int o = 16; o; o >>= 1) s += __shfl_xor_sync(0xffffffffu, s, o);
        if (lane == 0) s_g[j] = s;
    }
    __syncthreads();

    // c[d] = sum_j g_j xs[idx_j][d];  cc = <c,c>;  cr = <c,r>
    float cc = 0.f, cr = 0.f;
    for (int d = tid; d < ND; d += 128) {
        float c = 0.f;
        for (int j = 0; j < m; j++) c = fmaf(s_g[j], xs[(size_t)s_idx[j] * ND + d], c);
        cc = fmaf(c, c, cc);
        cr = fmaf(c, r[d], cr);
    }
#pragma unroll
    for (int o = 16; o; o >>= 1) {
        cc += __shfl_xor_sync(0xffffffffu, cc, o);
        cr += __shfl_xor_sync(0xffffffffu, cr, o);
    }
    if (lane == 0) { w_cc[warp] = cc; w_cr[warp] = cr; }
    __syncthreads();
    if (tid == 0) {
        float tcc = 0.f, tcr = 0.f;
        for (int wv = 0; wv < 4; wv++) { tcc += w_cc[wv]; tcr += w_cr[wv]; }
        s_step = tcr / fmaxf(tcc, EPSF);
    }
    __syncthreads();
    const float step = s_step;

    // relu update + compaction (serial on thread 0; m <= 32)
    if (tid == 0) {
        int nc = 0;
        for (int j = 0; j < m; j++) {
            float wn = fmaxf(s_w[j] + step * s_g[j], 0.f);
            if (wn > 0.f) { s_idx[nc] = s_idx[j]; s_w[nc] = wn; nc++; }
        }
        s_cnt = nc;
        g_cnt[b] = nc;
        for (int j = 0; j < nc; j++) { g_idx[b * L0 + j] = s_idx[j]; g_w[b * L0 + j] = s_w[j]; }
    }
    __syncthreads();
    const int nc = s_cnt;

    // rebuild residual for next iteration: r = x - sum_j w_j xs[idx_j]
    for (int d = tid; d < ND; d += 128) {
        float v = x[(size_t)b * ND + d];
        for (int j = 0; j < nc; j++) v = fmaf(-s_w[j], xs[(size_t)s_idx[j] * ND + d], v);
        g_res[(size_t)b * ND + d] = v;
    }
}

// ---------------- K4: top_k emulation + decode + losses ----------------
__global__ __launch_bounds__(256) void k_finalize(const float* __restrict__ y,
                                                  const float* __restrict__ xs,
                                                  const float* __restrict__ ys,
                                                  float* __restrict__ out) {
    const int b = blockIdx.x;
    const int tid = threadIdx.x;

    __shared__ int   s_idx[L0];
    __shared__ float s_w[L0];
    __shared__ int   s_m;
    __shared__ float wred[8];

    if (tid == 0) {
        int   ti[L0]; float tw[L0];
        int m = g_cnt[b];
        for (int j = 0; j < m; j++) { ti[j] = g_idx[b * L0 + j]; tw[j] = g_w[b * L0 + j]; }
        // stable sort: value desc, index asc on ties (matches jax.lax.top_k)
        for (int i = 1; i < m; i++) {
            float wv = tw[i]; int iv = ti[i]; int j = i - 1;
            while (j >= 0 && (tw[j] < wv || (tw[j] == wv && ti[j] > iv))) {
                tw[j + 1] = tw[j]; ti[j + 1] = ti[j]; j--;
            }
            tw[j + 1] = wv; ti[j + 1] = iv;
        }
        // zero-pad with smallest indices whose weight is zero (top_k tie rule)
        int k = m, f = 0;
        while (k < L0) {
            bool used = false;
            for (int j = 0; j < m; j++) if (ti[j] == f) { used = true; break; }
            if (!used) { ti[k] = f; tw[k] = 0.f; k++; }
            f++;
        }
        for (int j = 0; j < L0; j++) { s_idx[j] = ti[j]; s_w[j] = tw[j]; }
        s_m = m;
    }
    __syncthreads();

    float* out_w = out;                                 // [B,L0]
    float* out_i = out + (size_t)NB * L0;               // [B,L0] (indices as float)
    float* out_x = out + (size_t)2 * NB * L0;           // [B,D]
    float* out_y = out_x + (size_t)NB * ND;             // [B,D]
    float* out_l = out_y + (size_t)NB * ND;             // [B]

    if (tid < L0) {
        out_w[b * L0 + tid] = s_w[tid];
        out_i[b * L0 + tid] = (float)s_idx[tid];
    }

    const int m = s_m;
    float lsum = 0.f;
    for (int d = tid; d < ND; d += 256) {
        float vx = 0.f, vy = 0.f;
        for (int j = 0; j < m; j++) {
            const float w = s_w[j];
            const size_t f = (size_t)s_idx[j];
            vx = fmaf(w, xs[f * ND + d], vx);
            vy = fmaf(w, ys[f * ND + d], vy);
        }
        out_x[(size_t)b * ND + d] = vx;
        out_y[(size_t)b * ND + d] = vy;
        const float e = vy - y[(size_t)b * ND + d];
        lsum = fmaf(e, e, lsum);
    }
#pragma unroll
    for (int o = 16; o; o >>= 1) lsum += __shfl_xor_sync(0xffffffffu, lsum, o);
    if ((tid & 31) == 0) wred[tid >> 5] = lsum;
    __syncthreads();
    if (tid == 0) {
        float t = 0.f;
        for (int i = 0; i < 8; i++) t += wred[i];
        out_l[b] = t;
    }
}

// ---------------- host launcher ----------------
extern "C" void kernel_launch(void* const* d_in, const int* in_sizes, int n_in,
                              void* d_out, int out_size) {
    // Map inputs robustly by size: first two of B*D elems -> x,y; first two of F*D -> xs,ys.
    const float* x = nullptr; const float* y = nullptr;
    const float* xs = nullptr; const float* ys = nullptr;
    for (int i = 0; i < n_in; i++) {
        if (in_sizes[i] == NB * ND) { if (!x) x = (const float*)d_in[i]; else if (!y) y = (const float*)d_in[i]; }
        else if (in_sizes[i] == NF * ND) { if (!xs) xs = (const float*)d_in[i]; else if (!ys) ys = (const float*)d_in[i]; }
    }
    float* out = (float*)d_out;

    k_init<<<(NB * ND + 255) / 256, 256>>>(x);
    const int nblocks = (NF / BN) * (NB / BM);   // 256 * 8 = 2048
    for (int t = 0; t < L0; t++) {
        k_gemm_argmax<<<nblocks, NTHREADS>>>(xs);
        k_update<<<NB, 128>>>(x, xs);
    }
    k_finalize<<<NB, 256>>>(y, xs, ys, out);
}

// round 4
// speedup vs baseline: 4.6441x; 2.8105x over previous
#include <cuda_runtime.h>
#include <cuda_fp16.h>
#include <stdint.h>

// Problem constants (B, D, F, target_l0) — fixed by the dataset.
#define NB 1024
#define ND 1024
#define NF 32768
#define L0 32
#define EPSF 1e-3f

// ---------------- device state (no allocations allowed) ----------------
__device__ float              g_res[NB * ND];            // residual [B,D] fp32 (exact path)
__device__ __half             g_rhi[NB * ND];            // residual fp16 hi
__device__ __half             g_rlo[NB * ND];            // residual fp16 lo
__device__ __half             g_xhi[(size_t)NF * ND];    // xs fp16 hi
__device__ __half             g_xlo[(size_t)NF * ND];    // xs fp16 lo
__device__ float              g_w[NB * L0];
__device__ int                g_idx[NB * L0];
__device__ int                g_cnt[NB];
__device__ unsigned long long g_key[NB];

// ---------------- helpers ----------------
__device__ __forceinline__ uint32_t smem_to_u32(const void* p) {
    uint32_t a;
    asm("{ .reg .u64 t; cvta.to.shared.u64 t, %1; cvt.u32.u64 %0, t; }" : "=r"(a) : "l"(p));
    return a;
}

// pack (value, index): larger key == (larger value, then smaller index)
__device__ __forceinline__ unsigned long long pack_key(float v, int idx) {
    unsigned u = __float_as_uint(v);
    u = (u & 0x80000000u) ? ~u : (u | 0x80000000u);
    return ((unsigned long long)u << 32) | (unsigned)(0xFFFFFFFFu - (unsigned)idx);
}

__device__ __forceinline__ void split2h(float v, __half& hi, __half& lo) {
    hi = __float2half_rn(v);
    lo = __float2half_rn(v - __half2float(hi));
}

#define LDSM4(f, addr)                                                                 \
    asm volatile("ldmatrix.sync.aligned.m8n8.x4.shared.b16 {%0,%1,%2,%3}, [%4];"       \
                 : "=r"((f)[0]), "=r"((f)[1]), "=r"((f)[2]), "=r"((f)[3]) : "r"(addr))

#define MMA16816(d, a, b0, b1)                                                         \
    asm volatile("mma.sync.aligned.m16n8k16.row.col.f32.f16.f16.f32 "                  \
                 "{%0,%1,%2,%3},{%4,%5,%6,%7},{%8,%9},{%0,%1,%2,%3};"                  \
                 : "+f"((d)[0]), "+f"((d)[1]), "+f"((d)[2]), "+f"((d)[3])              \
                 : "r"((a)[0]), "r"((a)[1]), "r"((a)[2]), "r"((a)[3]),                 \
                   "r"(b0), "r"(b1))

#define CP_ASYNC16(sa, gp) \
    asm volatile("cp.async.cg.shared.global [%0], [%1], 16;" :: "r"(sa), "l"(gp))
#define CP_COMMIT()  asm volatile("cp.async.commit_group;")
#define CP_WAIT(n)   asm volatile("cp.async.wait_group %0;" :: "n"(n))

// ---------------- K-1: one-time split of xs into fp16 hi/lo ----------------
__global__ void k_split_xs(const float* __restrict__ xs) {
    size_t i = (size_t)blockIdx.x * blockDim.x + threadIdx.x;
    size_t n4 = (size_t)NF * ND / 4;
    if (i >= n4) return;
    float4 v = ((const float4*)xs)[i];
    __half h0, l0, h1, l1, h2, l2, h3, l3;
    split2h(v.x, h0, l0); split2h(v.y, h1, l1);
    split2h(v.z, h2, l2); split2h(v.w, h3, l3);
    __half2* ph = (__half2*)g_xhi;
    __half2* pl = (__half2*)g_xlo;
    ph[i * 2 + 0] = __half2(h0, h1);
    ph[i * 2 + 1] = __half2(h2, h3);
    pl[i * 2 + 0] = __half2(l0, l1);
    pl[i * 2 + 1] = __half2(l2, l3);
}

// ---------------- K0: init ----------------
__global__ void k_init(const float* __restrict__ x) {
    int i = blockIdx.x * blockDim.x + threadIdx.x;
    if (i < NB * ND) {
        float v = x[i];
        g_res[i] = v;
        __half h, l; split2h(v, h, l);
        g_rhi[i] = h; g_rlo[i] = l;
    }
    if (i < NB) { g_cnt[i] = 0; g_key[i] = 0ull; }
}

// ---------------- K2: fp16x3 split GEMM (mma.sync) + per-row argmax ----------------
// C[b][f] = sum_d res[b][d]*xs[f][d], computed as aH*bH + aH*bL + aL*bH in fp32 accum.
// CTA tile 128(M) x 128(N), BK=64 (128B fp16 rows, XOR-128 swizzle), 2-stage cp.async.
#define MAT_BYTES 16384                 // 128 rows * 128B
#define STAGE_BYTES (4 * MAT_BYTES)     // aH, aL, bH, bL
#define GSMEM (2 * STAGE_BYTES)         // 131072

__device__ __forceinline__ void fill_stage(uint32_t st, int k0, int tid,
                                           const __half* aH, const __half* aL,
                                           const __half* bH, const __half* bL) {
#pragma unroll
    for (int it = 0; it < 16; it++) {
        const int mat = it >> 2;                 // compile-time per it
        const int w = (it & 3) * 256 + tid;      // 0..1023 within matrix
        const int row = w >> 3;
        const int c = w & 7;
        const __half* base = (mat == 0) ? aH : (mat == 1) ? aL : (mat == 2) ? bH : bL;
        const __half* gp = base + (size_t)row * ND + k0 + c * 8;
        uint32_t off = (uint32_t)(row * 128 + ((c ^ (row & 7)) * 16));
        CP_ASYNC16(st + mat * MAT_BYTES + off, gp);
    }
    CP_COMMIT();
}

__global__ __launch_bounds__(256, 1) void k_gemm_mma() {
    extern __shared__ char smem[];
    const uint32_t sb = smem_to_u32(smem);

    const int tid = threadIdx.x;
    const int lane = tid & 31;
    const int wid = tid >> 5;
    const int wm = wid >> 1;      // 0..3 (M)
    const int wn = wid & 1;       // 0..1 (N)
    const int mi = lane >> 3;     // ldmatrix sub-matrix id group
    const int r8 = lane & 7;

    const int id = blockIdx.x;
    const int by = id & 7;        // 8 M tiles vary fastest -> 8 CTAs share B tile in L2
    const int bx = id >> 3;       // 256 N tiles
    const int row0 = by * 128;
    const int col0 = bx * 128;

    const __half* aH = g_rhi + (size_t)row0 * ND;
    const __half* aL = g_rlo + (size_t)row0 * ND;
    const __half* bH = g_xhi + (size_t)col0 * ND;
    const __half* bL = g_xlo + (size_t)col0 * ND;

    float acc[2][8][4];
#pragma unroll
    for (int i = 0; i < 2; i++)
#pragma unroll
        for (int j = 0; j < 8; j++)
#pragma unroll
            for (int q = 0; q < 4; q++) acc[i][j][q] = 0.f;

    // prologue: load stages 0 and 1
    fill_stage(sb, 0, tid, aH, aL, bH, bL);
    fill_stage(sb + STAGE_BYTES, 64, tid, aH, aL, bH, bL);
    CP_WAIT(1);
    __syncthreads();

    int buf = 0;
    for (int cch = 0; cch < 16; cch++) {
        const uint32_t st = sb + buf * STAGE_BYTES;

        // ---- compute this stage: 4 k16 steps ----
#pragma unroll
        for (int k16 = 0; k16 < 4; k16++) {
            uint32_t afr[2][2][4];   // [half][mt]
#pragma unroll
            for (int mt = 0; mt < 2; mt++) {
                const int row = wm * 32 + mt * 16 + (mi & 1) * 8 + r8;
                const int kc = k16 * 2 + (mi >> 1);
                const uint32_t off = (uint32_t)(row * 128 + ((kc ^ (row & 7)) * 16));
                LDSM4(afr[0][mt], st + off);
                LDSM4(afr[1][mt], st + MAT_BYTES + off);
            }
            uint32_t bfr[2][4][4];   // [half][nt16]
#pragma unroll
            for (int nt = 0; nt < 4; nt++) {
                const int row = wn * 64 + nt * 16 + (mi >> 1) * 8 + r8;
                const int kc = k16 * 2 + (mi & 1);
                const uint32_t off = (uint32_t)(row * 128 + ((kc ^ (row & 7)) * 16));
                LDSM4(bfr[0][nt], st + 2 * MAT_BYTES + off);
                LDSM4(bfr[1][nt], st + 3 * MAT_BYTES + off);
            }
#pragma unroll
            for (int mt = 0; mt < 2; mt++)
#pragma unroll
                for (int nt = 0; nt < 4; nt++)
#pragma unroll
                    for (int s = 0; s < 2; s++) {
                        float* d = acc[mt][nt * 2 + s];
                        MMA16816(d, afr[0][mt], bfr[0][nt][s * 2], bfr[0][nt][s * 2 + 1]); // hi*hi
                        MMA16816(d, afr[0][mt], bfr[1][nt][s * 2], bfr[1][nt][s * 2 + 1]); // hi*lo
                        MMA16816(d, afr[1][mt], bfr[0][nt][s * 2], bfr[0][nt][s * 2 + 1]); // lo*hi
                    }
        }

        __syncthreads();   // all warps done reading buf before refill
        if (cch + 2 < 16) {
            fill_stage(sb + buf * STAGE_BYTES, (cch + 2) * 64, tid, aH, aL, bH, bL);
            CP_WAIT(1);    // previous stage (cch+1) complete; just-issued may pend
        } else {
            CP_WAIT(0);    // drain for the final stage
        }
        __syncthreads();
        buf ^= 1;
    }

    // ---- epilogue: per-row argmax ----
#pragma unroll
    for (int mt = 0; mt < 2; mt++) {
#pragma unroll
        for (int goff = 0; goff < 2; goff++) {
            const int row = row0 + wm * 32 + mt * 16 + goff * 8 + (lane >> 2);
            unsigned long long best = 0ull;
#pragma unroll
            for (int nt = 0; nt < 8; nt++) {
                const int col = col0 + wn * 64 + nt * 8 + (lane & 3) * 2;
                unsigned long long k0 = pack_key(acc[mt][nt][goff * 2 + 0], col);
                unsigned long long k1 = pack_key(acc[mt][nt][goff * 2 + 1], col + 1);
                if (k0 > best) best = k0;
                if (k1 > best) best = k1;
            }
#pragma unroll
            for (int o = 1; o < 4; o <<= 1) {
                unsigned long long other = __shfl_xor_sync(0xffffffffu, best, o);
                if (other > best) best = other;
            }
            if ((lane & 3) == 0)
                atomicMax(&g_key[row], best);
        }
    }
}

// ---------------- K3: per-row update ----------------
__global__ __launch_bounds__(128) void k_update(const float* __restrict__ x,
                                                const float* __restrict__ xs) {
    const int b = blockIdx.x;
    const int tid = threadIdx.x;
    const int warp = tid >> 5, lane = tid & 31;

    __shared__ int   s_idx[L0];
    __shared__ float s_w[L0];
    __shared__ float s_g[L0];
    __shared__ int   s_cnt;
    __shared__ float s_step;
    __shared__ float w_cc[4], w_cr[4];

    if (tid == 0) {
        int cnt = g_cnt[b];
        for (int j = 0; j < cnt; j++) { s_idx[j] = g_idx[b * L0 + j]; s_w[j] = g_w[b * L0 + j]; }
        unsigned long long key = g_key[b];
        int f = (int)(0xFFFFFFFFu - (unsigned)(key & 0xFFFFFFFFull));
        bool present = false;
        for (int j = 0; j < cnt; j++) if (s_idx[j] == f) { present = true; break; }
        if (!present) { s_idx[cnt] = f; s_w[cnt] = 0.f; cnt++; }
        s_cnt = cnt;
        g_key[b] = 0ull;
    }
    __syncthreads();
    const int m = s_cnt;
    const float* r = g_res + (size_t)b * ND;

    for (int j = warp; j < m; j += 4) {
        const float* a = xs + (size_t)s_idx[j] * ND;
        float s = 0.f;
        for (int d = lane; d < ND; d += 32) s = fmaf(r[d], a[d], s);
#pragma unroll
        for (int o = 16; o; o >>= 1) s += __shfl_xor_sync(0xffffffffu, s, o);
        if (lane == 0) s_g[j] = s;
    }
    __syncthreads();

    float cc = 0.f, cr = 0.f;
    for (int d = tid; d < ND; d += 128) {
        float c = 0.f;
        for (int j = 0; j < m; j++) c = fmaf(s_g[j], xs[(size_t)s_idx[j] * ND + d], c);
        cc = fmaf(c, c, cc);
        cr = fmaf(c, r[d], cr);
    }
#pragma unroll
    for (int o = 16; o; o >>= 1) {
        cc += __shfl_xor_sync(0xffffffffu, cc, o);
        cr += __shfl_xor_sync(0xffffffffu, cr, o);
    }
    if (lane == 0) { w_cc[warp] = cc; w_cr[warp] = cr; }
    __syncthreads();
    if (tid == 0) {
        float tcc = 0.f, tcr = 0.f;
        for (int wv = 0; wv < 4; wv++) { tcc += w_cc[wv]; tcr += w_cr[wv]; }
        s_step = tcr / fmaxf(tcc, EPSF);
    }
    __syncthreads();
    const float step = s_step;

    if (tid == 0) {
        int nc = 0;
        for (int j = 0; j < m; j++) {
            float wn2 = fmaxf(s_w[j] + step * s_g[j], 0.f);
            if (wn2 > 0.f) { s_idx[nc] = s_idx[j]; s_w[nc] = wn2; nc++; }
        }
        s_cnt = nc;
        g_cnt[b] = nc;
        for (int j = 0; j < nc; j++) { g_idx[b * L0 + j] = s_idx[j]; g_w[b * L0 + j] = s_w[j]; }
    }
    __syncthreads();
    const int nc = s_cnt;

    // rebuild residual (fp32) + fp16 hi/lo split for the tensor GEMM
    for (int d = tid; d < ND; d += 128) {
        float v = x[(size_t)b * ND + d];
        for (int j = 0; j < nc; j++) v = fmaf(-s_w[j], xs[(size_t)s_idx[j] * ND + d], v);
        g_res[(size_t)b * ND + d] = v;
        __half h, l; split2h(v, h, l);
        g_rhi[(size_t)b * ND + d] = h;
        g_rlo[(size_t)b * ND + d] = l;
    }
}

// ---------------- K4: top_k emulation + decode + losses ----------------
__global__ __launch_bounds__(256) void k_finalize(const float* __restrict__ y,
                                                  const float* __restrict__ xs,
                                                  const float* __restrict__ ys,
                                                  float* __restrict__ out) {
    const int b = blockIdx.x;
    const int tid = threadIdx.x;

    __shared__ int   s_idx[L0];
    __shared__ float s_w[L0];
    __shared__ int   s_m;
    __shared__ float wred[8];

    if (tid == 0) {
        int   ti[L0]; float tw[L0];
        int m = g_cnt[b];
        for (int j = 0; j < m; j++) { ti[j] = g_idx[b * L0 + j]; tw[j] = g_w[b * L0 + j]; }
        // stable sort: value desc, index asc on ties (matches jax.lax.top_k)
        for (int i = 1; i < m; i++) {
            float wv = tw[i]; int iv = ti[i]; int j = i - 1;
            while (j >= 0 && (tw[j] < wv || (tw[j] == wv && ti[j] > iv))) {
                tw[j + 1] = tw[j]; ti[j + 1] = ti[j]; j--;
            }
            tw[j + 1] = wv; ti[j + 1] = iv;
        }
        // zero-pad with smallest unused indices (top_k tie rule on zeros)
        int k = m, f = 0;
        while (k < L0) {
            bool used = false;
            for (int j = 0; j < m; j++) if (ti[j] == f) { used = true; break; }
            if (!used) { ti[k] = f; tw[k] = 0.f; k++; }
            f++;
        }
        for (int j = 0; j < L0; j++) { s_idx[j] = ti[j]; s_w[j] = tw[j]; }
        s_m = m;
    }
    __syncthreads();

    float* out_w = out;
    float* out_i = out + (size_t)NB * L0;
    float* out_x = out + (size_t)2 * NB * L0;
    float* out_y = out_x + (size_t)NB * ND;
    float* out_l = out_y + (size_t)NB * ND;

    if (tid < L0) {
        out_w[b * L0 + tid] = s_w[tid];
        out_i[b * L0 + tid] = (float)s_idx[tid];
    }

    const int m = s_m;
    float lsum = 0.f;
    for (int d = tid; d < ND; d += 256) {
        float vx = 0.f, vy = 0.f;
        for (int j = 0; j < m; j++) {
            const float w = s_w[j];
            const size_t f = (size_t)s_idx[j];
            vx = fmaf(w, xs[f * ND + d], vx);
            vy = fmaf(w, ys[f * ND + d], vy);
        }
        out_x[(size_t)b * ND + d] = vx;
        out_y[(size_t)b * ND + d] = vy;
        const float e = vy - y[(size_t)b * ND + d];
        lsum = fmaf(e, e, lsum);
    }
#pragma unroll
    for (int o = 16; o; o >>= 1) lsum += __shfl_xor_sync(0xffffffffu, lsum, o);
    if ((tid & 31) == 0) wred[tid >> 5] = lsum;
    __syncthreads();
    if (tid == 0) {
        float t = 0.f;
        for (int i = 0; i < 8; i++) t += wred[i];
        out_l[b] = t;
    }
}

// ---------------- host launcher ----------------
extern "C" void kernel_launch(void* const* d_in, const int* in_sizes, int n_in,
                              void* d_out, int out_size) {
    const float* x = nullptr; const float* y = nullptr;
    const float* xs = nullptr; const float* ys = nullptr;
    for (int i = 0; i < n_in; i++) {
        if (in_sizes[i] == NB * ND) { if (!x) x = (const float*)d_in[i]; else if (!y) y = (const float*)d_in[i]; }
        else if (in_sizes[i] == NF * ND) { if (!xs) xs = (const float*)d_in[i]; else if (!ys) ys = (const float*)d_in[i]; }
    }
    float* out = (float*)d_out;

    cudaFuncSetAttribute(k_gemm_mma, cudaFuncAttributeMaxDynamicSharedMemorySize, GSMEM);

    {   // one-time fp16 split of xs (idempotent, deterministic)
        size_t n4 = (size_t)NF * ND / 4;
        k_split_xs<<<(unsigned)((n4 + 255) / 256), 256>>>(xs);
    }
    k_init<<<(NB * ND + 255) / 256, 256>>>(x);

    const int ngrid = (NF / 128) * (NB / 128);   // 256 * 8 = 2048
    for (int t = 0; t < L0; t++) {
        k_gemm_mma<<<ngrid, 256, GSMEM>>>();
        k_update<<<NB, 128>>>(x, xs);
    }
    k_finalize<<<NB, 256>>>(y, xs, ys, out);
}

// round 5
// speedup vs baseline: 9.2139x; 1.9840x over previous
#include <cuda_runtime.h>
#include <cuda_fp16.h>
#include <stdint.h>

// Problem constants (B, D, F, target_l0) — fixed by the dataset.
#define NB 1024
#define ND 1024
#define NF 32768
#define L0 32
#define EPSF 1e-3f

// ---------------- device state (no allocations allowed) ----------------
__device__ float              g_res[NB * ND];            // residual [B,D] fp32 (exact path)
__device__ float              g_rnorm[NB];               // ||r|| per row
__device__ __half             g_rhi[NB * ND];            // residual fp16 (hi)
__device__ __half             g_xhi[(size_t)NF * ND];    // xs fp16 (hi)
__device__ __half             g_C[(size_t)NB * NF];      // approx inner products
__device__ float              g_w[NB * L0];
__device__ int                g_idx[NB * L0];
__device__ int                g_cnt[NB];
__device__ unsigned long long g_key[NB];

// ---------------- helpers ----------------
__device__ __forceinline__ uint32_t smem_to_u32(const void* p) {
    uint32_t a;
    asm("{ .reg .u64 t; cvta.to.shared.u64 t, %1; cvt.u32.u64 %0, t; }" : "=r"(a) : "l"(p));
    return a;
}

// pack (value, index): larger key == (larger value, then smaller index)
__device__ __forceinline__ unsigned long long pack_key(float v, int idx) {
    unsigned u = __float_as_uint(v);
    u = (u & 0x80000000u) ? ~u : (u | 0x80000000u);
    return ((unsigned long long)u << 32) | (unsigned)(0xFFFFFFFFu - (unsigned)idx);
}

#define LDSM4(f, addr)                                                                 \
    asm volatile("ldmatrix.sync.aligned.m8n8.x4.shared.b16 {%0,%1,%2,%3}, [%4];"       \
                 : "=r"((f)[0]), "=r"((f)[1]), "=r"((f)[2]), "=r"((f)[3]) : "r"(addr))

#define MMA16816(d, a, b0, b1)                                                         \
    asm volatile("mma.sync.aligned.m16n8k16.row.col.f32.f16.f16.f32 "                  \
                 "{%0,%1,%2,%3},{%4,%5,%6,%7},{%8,%9},{%0,%1,%2,%3};"                  \
                 : "+f"((d)[0]), "+f"((d)[1]), "+f"((d)[2]), "+f"((d)[3])              \
                 : "r"((a)[0]), "r"((a)[1]), "r"((a)[2]), "r"((a)[3]),                 \
                   "r"(b0), "r"(b1))

#define CP_ASYNC16(sa, gp) \
    asm volatile("cp.async.cg.shared.global [%0], [%1], 16;" :: "r"(sa), "l"(gp))
#define CP_COMMIT()  asm volatile("cp.async.commit_group;")
#define CP_WAIT(n)   asm volatile("cp.async.wait_group %0;" :: "n"(n))

// ---------------- K-1: one-time fp16 cast of xs ----------------
__global__ void k_split_xs(const float* __restrict__ xs) {
    size_t i = (size_t)blockIdx.x * blockDim.x + threadIdx.x;
    size_t n4 = (size_t)NF * ND / 4;
    if (i >= n4) return;
    float4 v = ((const float4*)xs)[i];
    __half2* ph = (__half2*)g_xhi;
    ph[i * 2 + 0] = __half2(__float2half_rn(v.x), __float2half_rn(v.y));
    ph[i * 2 + 1] = __half2(__float2half_rn(v.z), __float2half_rn(v.w));
}

// ---------------- K0: init ----------------
__global__ void k_init(const float* __restrict__ x) {
    int i = blockIdx.x * blockDim.x + threadIdx.x;
    if (i < NB * ND) {
        float v = x[i];
        g_res[i] = v;
        g_rhi[i] = __float2half_rn(v);
    }
    if (i < NB) { g_cnt[i] = 0; g_key[i] = 0ull; }
}

// initial residual norms
__global__ __launch_bounds__(256) void k_norm0() {
    const int b = blockIdx.x;
    const int tid = threadIdx.x;
    __shared__ float wr[8];
    float nn = 0.f;
    for (int d = tid; d < ND; d += 256) {
        float v = g_res[(size_t)b * ND + d];
        nn = fmaf(v, v, nn);
    }
#pragma unroll
    for (int o = 16; o; o >>= 1) nn += __shfl_xor_sync(0xffffffffu, nn, o);
    if ((tid & 31) == 0) wr[tid >> 5] = nn;
    __syncthreads();
    if (tid == 0) {
        float t = 0.f;
        for (int i = 0; i < 8; i++) t += wr[i];
        g_rnorm[b] = sqrtf(t);
    }
}

// ---------------- K2: fp16 hi*hi GEMM (mma.sync), store C fp16 ----------------
// CTA tile 128(M) x 128(N), BK=64 (128B fp16 rows, XOR swizzle), 2-stage cp.async.
#define MAT_BYTES 16384                 // 128 rows * 128B
#define STAGE_BYTES (2 * MAT_BYTES)     // aH, bH
#define GSMEM (2 * STAGE_BYTES)         // 65536

__device__ __forceinline__ void fill_stage(uint32_t st, int k0, int tid,
                                           const __half* aH, const __half* bH) {
#pragma unroll
    for (int it = 0; it < 8; it++) {
        const int mat = it >> 2;                 // 0 = A, 1 = B
        const int w = (it & 3) * 256 + tid;      // 0..1023 within matrix
        const int row = w >> 3;
        const int c = w & 7;
        const __half* base = mat ? bH : aH;
        const __half* gp = base + (size_t)row * ND + k0 + c * 8;
        uint32_t off = (uint32_t)(row * 128 + ((c ^ (row & 7)) * 16));
        CP_ASYNC16(st + mat * MAT_BYTES + off, gp);
    }
    CP_COMMIT();
}

__global__ __launch_bounds__(256, 2) void k_gemm_mma() {
    extern __shared__ char smem[];
    const uint32_t sb = smem_to_u32(smem);

    const int tid = threadIdx.x;
    const int lane = tid & 31;
    const int wid = tid >> 5;
    const int wm = wid >> 1;      // 0..3 (M)
    const int wn = wid & 1;       // 0..1 (N)
    const int mi = lane >> 3;
    const int r8 = lane & 7;

    const int id = blockIdx.x;
    const int by = id & 7;        // M tiles vary fastest -> CTAs share B tile in L2
    const int bx = id >> 3;
    const int row0 = by * 128;
    const int col0 = bx * 128;

    const __half* aH = g_rhi + (size_t)row0 * ND;
    const __half* bH = g_xhi + (size_t)col0 * ND;

    float acc[2][8][4];
#pragma unroll
    for (int i = 0; i < 2; i++)
#pragma unroll
        for (int j = 0; j < 8; j++)
#pragma unroll
            for (int q = 0; q < 4; q++) acc[i][j][q] = 0.f;

    fill_stage(sb, 0, tid, aH, bH);
    fill_stage(sb + STAGE_BYTES, 64, tid, aH, bH);
    CP_WAIT(1);
    __syncthreads();

    int buf = 0;
    for (int cch = 0; cch < 16; cch++) {
        const uint32_t st = sb + buf * STAGE_BYTES;

#pragma unroll
        for (int k16 = 0; k16 < 4; k16++) {
            uint32_t afr[2][4];
#pragma unroll
            for (int mt = 0; mt < 2; mt++) {
                const int row = wm * 32 + mt * 16 + (mi & 1) * 8 + r8;
                const int kc = k16 * 2 + (mi >> 1);
                const uint32_t off = (uint32_t)(row * 128 + ((kc ^ (row & 7)) * 16));
                LDSM4(afr[mt], st + off);
            }
            uint32_t bfr[4][4];
#pragma unroll
            for (int nt = 0; nt < 4; nt++) {
                const int row = wn * 64 + nt * 16 + (mi >> 1) * 8 + r8;
                const int kc = k16 * 2 + (mi & 1);
                const uint32_t off = (uint32_t)(row * 128 + ((kc ^ (row & 7)) * 16));
                LDSM4(bfr[nt], st + MAT_BYTES + off);
            }
#pragma unroll
            for (int mt = 0; mt < 2; mt++)
#pragma unroll
                for (int nt = 0; nt < 4; nt++)
#pragma unroll
                    for (int s = 0; s < 2; s++)
                        MMA16816(acc[mt][nt * 2 + s], afr[mt],
                                 bfr[nt][s * 2], bfr[nt][s * 2 + 1]);
        }

        __syncthreads();
        if (cch + 2 < 16) {
            fill_stage(sb + buf * STAGE_BYTES, (cch + 2) * 64, tid, aH, bH);
            CP_WAIT(1);
        } else {
            CP_WAIT(0);
        }
        __syncthreads();
        buf ^= 1;
    }

    // ---- epilogue: store C tile as fp16 ----
    __half2* C2 = (__half2*)g_C;
#pragma unroll
    for (int mt = 0; mt < 2; mt++) {
#pragma unroll
        for (int j = 0; j < 8; j++) {
            const int row = row0 + wm * 32 + mt * 16 + (lane >> 2);
            const int col = col0 + wn * 64 + j * 8 + (lane & 3) * 2;
            C2[(size_t)row * (NF / 2) + (col >> 1)] =
                __half2(__float2half_rn(acc[mt][j][0]), __float2half_rn(acc[mt][j][1]));
            C2[(size_t)(row + 8) * (NF / 2) + (col >> 1)] =
                __half2(__float2half_rn(acc[mt][j][2]), __float2half_rn(acc[mt][j][3]));
        }
    }
}

// ---------------- K2b: rescue — scan C, rescore candidates exactly ----------------
#define MAXCAND 128
__global__ __launch_bounds__(256) void k_rescue(const float* __restrict__ xs) {
    const int b = blockIdx.x;
    const int tid = threadIdx.x;
    const int lane = tid & 31;

    __shared__ float s_max;
    __shared__ float wr[8];
    __shared__ int   s_cand[MAXCAND];
    __shared__ int   s_nc;
    __shared__ unsigned long long s_best;

    const __half2* Crow = (const __half2*)g_C + (size_t)b * (NF / 2);

    // phase 1: row max of stored values
    float mx = -1e30f;
    for (int i = tid; i < NF / 2; i += 256) {
        __half2 v = Crow[i];
        float a = __half2float(v.x), c = __half2float(v.y);
        mx = fmaxf(mx, fmaxf(a, c));
    }
#pragma unroll
    for (int o = 16; o; o >>= 1) mx = fmaxf(mx, __shfl_xor_sync(0xffffffffu, mx, o));
    if (lane == 0) wr[tid >> 5] = mx;
    if (tid == 0) s_nc = 0;
    __syncthreads();
    if (tid == 0) {
        float t = -1e30f;
        for (int i = 0; i < 8; i++) t = fmaxf(t, wr[i]);
        s_max = t;
    }
    __syncthreads();

    // deterministic error bound: |stored - exact| <= ~1.5e-3 * ||r||; use 2e-3 slack
    const float Bm = 2.0e-3f * g_rnorm[b] + 1e-7f;
    const float thr = s_max - 2.f * Bm;

    // phase 2: collect candidates
    for (int i = tid; i < NF / 2; i += 256) {
        __half2 v = Crow[i];
        float a = __half2float(v.x), c = __half2float(v.y);
        if (a >= thr) { int p = atomicAdd(&s_nc, 1); if (p < MAXCAND) s_cand[p] = 2 * i; }
        if (c >= thr) { int p = atomicAdd(&s_nc, 1); if (p < MAXCAND) s_cand[p] = 2 * i + 1; }
    }
    __syncthreads();
    const int nc = (s_nc < MAXCAND) ? s_nc : MAXCAND;
    if (tid == 0) s_best = 0ull;

    // phase 3: exact fp32 rescore of each candidate
    const float* r = g_res + (size_t)b * ND;
    for (int cdx = 0; cdx < nc; cdx++) {
        const int f = s_cand[cdx];
        const float* a = xs + (size_t)f * ND;
        float s = 0.f;
        for (int d = tid; d < ND; d += 256) s = fmaf(r[d], a[d], s);
#pragma unroll
        for (int o = 16; o; o >>= 1) s += __shfl_xor_sync(0xffffffffu, s, o);
        if (lane == 0) wr[tid >> 5] = s;
        __syncthreads();
        if (tid == 0) {
            float t = 0.f;
            for (int i = 0; i < 8; i++) t += wr[i];
            unsigned long long k = pack_key(t, f);
            if (k > s_best) s_best = k;
        }
        __syncthreads();
    }
    if (tid == 0) g_key[b] = s_best;
}

// ---------------- K3: per-row update ----------------
__global__ __launch_bounds__(128) void k_update(const float* __restrict__ x,
                                                const float* __restrict__ xs) {
    const int b = blockIdx.x;
    const int tid = threadIdx.x;
    const int warp = tid >> 5, lane = tid & 31;

    __shared__ int   s_idx[L0];
    __shared__ float s_w[L0];
    __shared__ float s_g[L0];
    __shared__ int   s_cnt;
    __shared__ float s_step;
    __shared__ float w_cc[4], w_cr[4], w_nn[4];

    if (tid == 0) {
        int cnt = g_cnt[b];
        for (int j = 0; j < cnt; j++) { s_idx[j] = g_idx[b * L0 + j]; s_w[j] = g_w[b * L0 + j]; }
        unsigned long long key = g_key[b];
        int f = (int)(0xFFFFFFFFu - (unsigned)(key & 0xFFFFFFFFull));
        bool present = false;
        for (int j = 0; j < cnt; j++) if (s_idx[j] == f) { present = true; break; }
        if (!present) { s_idx[cnt] = f; s_w[cnt] = 0.f; cnt++; }
        s_cnt = cnt;
    }
    __syncthreads();
    const int m = s_cnt;
    const float* r = g_res + (size_t)b * ND;

    for (int j = warp; j < m; j += 4) {
        const float* a = xs + (size_t)s_idx[j] * ND;
        float s = 0.f;
        for (int d = lane; d < ND; d += 32) s = fmaf(r[d], a[d], s);
#pragma unroll
        for (int o = 16; o; o >>= 1) s += __shfl_xor_sync(0xffffffffu, s, o);
        if (lane == 0) s_g[j] = s;
    }
    __syncthreads();

    float cc = 0.f, cr = 0.f;
    for (int d = tid; d < ND; d += 128) {
        float c = 0.f;
        for (int j = 0; j < m; j++) c = fmaf(s_g[j], xs[(size_t)s_idx[j] * ND + d], c);
        cc = fmaf(c, c, cc);
        cr = fmaf(c, r[d], cr);
    }
#pragma unroll
    for (int o = 16; o; o >>= 1) {
        cc += __shfl_xor_sync(0xffffffffu, cc, o);
        cr += __shfl_xor_sync(0xffffffffu, cr, o);
    }
    if (lane == 0) { w_cc[warp] = cc; w_cr[warp] = cr; }
    __syncthreads();
    if (tid == 0) {
        float tcc = 0.f, tcr = 0.f;
        for (int wv = 0; wv < 4; wv++) { tcc += w_cc[wv]; tcr += w_cr[wv]; }
        s_step = tcr / fmaxf(tcc, EPSF);
    }
    __syncthreads();
    const float step = s_step;

    if (tid == 0) {
        int nc = 0;
        for (int j = 0; j < m; j++) {
            float wn2 = fmaxf(s_w[j] + step * s_g[j], 0.f);
            if (wn2 > 0.f) { s_idx[nc] = s_idx[j]; s_w[nc] = wn2; nc++; }
        }
        s_cnt = nc;
        g_cnt[b] = nc;
        for (int j = 0; j < nc; j++) { g_idx[b * L0 + j] = s_idx[j]; g_w[b * L0 + j] = s_w[j]; }
    }
    __syncthreads();
    const int nc = s_cnt;

    // rebuild residual (fp32) + fp16 cast + norm for next iteration
    float nn = 0.f;
    for (int d = tid; d < ND; d += 128) {
        float v = x[(size_t)b * ND + d];
        for (int j = 0; j < nc; j++) v = fmaf(-s_w[j], xs[(size_t)s_idx[j] * ND + d], v);
        g_res[(size_t)b * ND + d] = v;
        g_rhi[(size_t)b * ND + d] = __float2half_rn(v);
        nn = fmaf(v, v, nn);
    }
#pragma unroll
    for (int o = 16; o; o >>= 1) nn += __shfl_xor_sync(0xffffffffu, nn, o);
    if (lane == 0) w_nn[warp] = nn;
    __syncthreads();
    if (tid == 0) {
        float t = 0.f;
        for (int wv = 0; wv < 4; wv++) t += w_nn[wv];
        g_rnorm[b] = sqrtf(t);
    }
}

// ---------------- K4: top_k emulation + decode + losses ----------------
__global__ __launch_bounds__(256) void k_finalize(const float* __restrict__ y,
                                                  const float* __restrict__ xs,
                                                  const float* __restrict__ ys,
                                                  float* __restrict__ out) {
    const int b = blockIdx.x;
    const int tid = threadIdx.x;

    __shared__ int   s_idx[L0];
    __shared__ float s_w[L0];
    __shared__ int   s_m;
    __shared__ float wred[8];

    if (tid == 0) {
        int   ti[L0]; float tw[L0];
        int m = g_cnt[b];
        for (int j = 0; j < m; j++) { ti[j] = g_idx[b * L0 + j]; tw[j] = g_w[b * L0 + j]; }
        // stable sort: value desc, index asc on ties (matches jax.lax.top_k)
        for (int i = 1; i < m; i++) {
            float wv = tw[i]; int iv = ti[i]; int j = i - 1;
            while (j >= 0 && (tw[j] < wv || (tw[j] == wv && ti[j] > iv))) {
                tw[j + 1] = tw[j]; ti[j + 1] = ti[j]; j--;
            }
            tw[j + 1] = wv; ti[j + 1] = iv;
        }
        // zero-pad with smallest unused indices (top_k tie rule on zeros)
        int k = m, f = 0;
        while (k < L0) {
            bool used = false;
            for (int j = 0; j < m; j++) if (ti[j] == f) { used = true; break; }
            if (!used) { ti[k] = f; tw[k] = 0.f; k++; }
            f++;
        }
        for (int j = 0; j < L0; j++) { s_idx[j] = ti[j]; s_w[j] = tw[j]; }
        s_m = m;
    }
    __syncthreads();

    float* out_w = out;
    float* out_i = out + (size_t)NB * L0;
    float* out_x = out + (size_t)2 * NB * L0;
    float* out_y = out_x + (size_t)NB * ND;
    float* out_l = out_y + (size_t)NB * ND;

    if (tid < L0) {
        out_w[b * L0 + tid] = s_w[tid];
        out_i[b * L0 + tid] = (float)s_idx[tid];
    }

    const int m = s_m;
    float lsum = 0.f;
    for (int d = tid; d < ND; d += 256) {
        float vx = 0.f, vy = 0.f;
        for (int j = 0; j < m; j++) {
            const float w = s_w[j];
            const size_t f = (size_t)s_idx[j];
            vx = fmaf(w, xs[f * ND + d], vx);
            vy = fmaf(w, ys[f * ND + d], vy);
        }
        out_x[(size_t)b * ND + d] = vx;
        out_y[(size_t)b * ND + d] = vy;
        const float e = vy - y[(size_t)b * ND + d];
        lsum = fmaf(e, e, lsum);
    }
#pragma unroll
    for (int o = 16; o; o >>= 1) lsum += __shfl_xor_sync(0xffffffffu, lsum, o);
    if ((tid & 31) == 0) wred[tid >> 5] = lsum;
    __syncthreads();
    if (tid == 0) {
        float t = 0.f;
        for (int i = 0; i < 8; i++) t += wred[i];
        out_l[b] = t;
    }
}

// ---------------- host launcher ----------------
extern "C" void kernel_launch(void* const* d_in, const int* in_sizes, int n_in,
                              void* d_out, int out_size) {
    const float* x = nullptr; const float* y = nullptr;
    const float* xs = nullptr; const float* ys = nullptr;
    for (int i = 0; i < n_in; i++) {
        if (in_sizes[i] == NB * ND) { if (!x) x = (const float*)d_in[i]; else if (!y) y = (const float*)d_in[i]; }
        else if (in_sizes[i] == NF * ND) { if (!xs) xs = (const float*)d_in[i]; else if (!ys) ys = (const float*)d_in[i]; }
    }
    float* out = (float*)d_out;

    cudaFuncSetAttribute(k_gemm_mma, cudaFuncAttributeMaxDynamicSharedMemorySize, GSMEM);

    {   // one-time fp16 cast of xs (idempotent, deterministic)
        size_t n4 = (size_t)NF * ND / 4;
        k_split_xs<<<(unsigned)((n4 + 255) / 256), 256>>>(xs);
    }
    k_init<<<(NB * ND + 255) / 256, 256>>>(x);
    k_norm0<<<NB, 256>>>();

    const int ngrid = (NF / 128) * (NB / 128);   // 256 * 8 = 2048
    for (int t = 0; t < L0; t++) {
        k_gemm_mma<<<ngrid, 256, GSMEM>>>();
        k_rescue<<<NB, 256>>>(xs);
        k_update<<<NB, 128>>>(x, xs);
    }
    k_finalize<<<NB, 256>>>(y, xs, ys, out);
}

// round 6
// speedup vs baseline: 10.8413x; 1.1766x over previous
#include <cuda_runtime.h>
#include <cuda_fp16.h>
#include <stdint.h>

// Problem constants (B, D, F, target_l0) — fixed by the dataset.
#define NB 1024
#define ND 1024
#define NF 32768
#define L0 32
#define EPSF 1e-3f
#define NTILE (NF / 128)        // 256 column tiles

// ---------------- device state (no allocations allowed) ----------------
__device__ float              g_res[NB * ND];            // residual [B,D] fp32 (exact path)
__device__ float              g_rnorm[NB];               // ||r|| per row
__device__ __half             g_rhi[NB * ND];            // residual fp16
__device__ __half             g_xhi[(size_t)NF * ND];    // xs fp16
__device__ __half             g_C[(size_t)NB * NF];      // approx inner products
__device__ float              g_tmax[NB][NTILE];         // per (row, 128-col tile) max (fp32 acc)
__device__ float              g_w[NB * L0];
__device__ int                g_idx[NB * L0];
__device__ int                g_cnt[NB];

// ---------------- helpers ----------------
__device__ __forceinline__ uint32_t smem_to_u32(const void* p) {
    uint32_t a;
    asm("{ .reg .u64 t; cvta.to.shared.u64 t, %1; cvt.u32.u64 %0, t; }" : "=r"(a) : "l"(p));
    return a;
}

// pack (value, index): larger key == (larger value, then smaller index)
__device__ __forceinline__ unsigned long long pack_key(float v, int idx) {
    unsigned u = __float_as_uint(v);
    u = (u & 0x80000000u) ? ~u : (u | 0x80000000u);
    return ((unsigned long long)u << 32) | (unsigned)(0xFFFFFFFFu - (unsigned)idx);
}

#define LDSM4(f, addr)                                                                 \
    asm volatile("ldmatrix.sync.aligned.m8n8.x4.shared.b16 {%0,%1,%2,%3}, [%4];"       \
                 : "=r"((f)[0]), "=r"((f)[1]), "=r"((f)[2]), "=r"((f)[3]) : "r"(addr))

#define MMA16816(d, a, b0, b1)                                                         \
    asm volatile("mma.sync.aligned.m16n8k16.row.col.f32.f16.f16.f32 "                  \
                 "{%0,%1,%2,%3},{%4,%5,%6,%7},{%8,%9},{%0,%1,%2,%3};"                  \
                 : "+f"((d)[0]), "+f"((d)[1]), "+f"((d)[2]), "+f"((d)[3])              \
                 : "r"((a)[0]), "r"((a)[1]), "r"((a)[2]), "r"((a)[3]),                 \
                   "r"(b0), "r"(b1))

#define CP_ASYNC16(sa, gp) \
    asm volatile("cp.async.cg.shared.global [%0], [%1], 16;" :: "r"(sa), "l"(gp))
#define CP_COMMIT()  asm volatile("cp.async.commit_group;")
#define CP_WAIT(n)   asm volatile("cp.async.wait_group %0;" :: "n"(n))

// ---------------- K-1: one-time fp16 cast of xs ----------------
__global__ void k_split_xs(const float* __restrict__ xs) {
    size_t i = (size_t)blockIdx.x * blockDim.x + threadIdx.x;
    size_t n4 = (size_t)NF * ND / 4;
    if (i >= n4) return;
    float4 v = ((const float4*)xs)[i];
    __half2* ph = (__half2*)g_xhi;
    ph[i * 2 + 0] = __half2(__float2half_rn(v.x), __float2half_rn(v.y));
    ph[i * 2 + 1] = __half2(__float2half_rn(v.z), __float2half_rn(v.w));
}

// ---------------- K0: init ----------------
__global__ void k_init(const float* __restrict__ x) {
    int i = blockIdx.x * blockDim.x + threadIdx.x;
    if (i < NB * ND) {
        float v = x[i];
        g_res[i] = v;
        g_rhi[i] = __float2half_rn(v);
    }
    if (i < NB) g_cnt[i] = 0;
}

// initial residual norms
__global__ __launch_bounds__(256) void k_norm0() {
    const int b = blockIdx.x;
    const int tid = threadIdx.x;
    __shared__ float wr[8];
    float nn = 0.f;
    for (int d = tid; d < ND; d += 256) {
        float v = g_res[(size_t)b * ND + d];
        nn = fmaf(v, v, nn);
    }
#pragma unroll
    for (int o = 16; o; o >>= 1) nn += __shfl_xor_sync(0xffffffffu, nn, o);
    if ((tid & 31) == 0) wr[tid >> 5] = nn;
    __syncthreads();
    if (tid == 0) {
        float t = 0.f;
        for (int i = 0; i < 8; i++) t += wr[i];
        g_rnorm[b] = sqrtf(t);
    }
}

// ---------------- K2: fp16 hi*hi GEMM (mma.sync), store C fp16 + per-tile max ----------------
// CTA tile 128(M) x 128(N), BK=64 (128B fp16 rows, XOR swizzle), 2-stage cp.async.
#define MAT_BYTES 16384                 // 128 rows * 128B
#define STAGE_BYTES (2 * MAT_BYTES)     // aH, bH
#define GSMEM (2 * STAGE_BYTES)         // 65536

__device__ __forceinline__ void fill_stage(uint32_t st, int k0, int tid,
                                           const __half* aH, const __half* bH) {
#pragma unroll
    for (int it = 0; it < 8; it++) {
        const int mat = it >> 2;                 // 0 = A, 1 = B
        const int w = (it & 3) * 256 + tid;      // 0..1023 within matrix
        const int row = w >> 3;
        const int c = w & 7;
        const __half* base = mat ? bH : aH;
        const __half* gp = base + (size_t)row * ND + k0 + c * 8;
        uint32_t off = (uint32_t)(row * 128 + ((c ^ (row & 7)) * 16));
        CP_ASYNC16(st + mat * MAT_BYTES + off, gp);
    }
    CP_COMMIT();
}

__global__ __launch_bounds__(256, 2) void k_gemm_mma() {
    extern __shared__ char smem[];
    const uint32_t sb = smem_to_u32(smem);

    const int tid = threadIdx.x;
    const int lane = tid & 31;
    const int wid = tid >> 5;
    const int wm = wid >> 1;      // 0..3 (M)
    const int wn = wid & 1;       // 0..1 (N)
    const int mi = lane >> 3;
    const int r8 = lane & 7;

    const int id = blockIdx.x;
    const int by = id & 7;        // M tiles vary fastest -> CTAs share B tile in L2
    const int bx = id >> 3;
    const int row0 = by * 128;
    const int col0 = bx * 128;

    const __half* aH = g_rhi + (size_t)row0 * ND;
    const __half* bH = g_xhi + (size_t)col0 * ND;

    float acc[2][8][4];
#pragma unroll
    for (int i = 0; i < 2; i++)
#pragma unroll
        for (int j = 0; j < 8; j++)
#pragma unroll
            for (int q = 0; q < 4; q++) acc[i][j][q] = 0.f;

    fill_stage(sb, 0, tid, aH, bH);
    fill_stage(sb + STAGE_BYTES, 64, tid, aH, bH);
    CP_WAIT(1);
    __syncthreads();

    int buf = 0;
    for (int cch = 0; cch < 16; cch++) {
        const uint32_t st = sb + buf * STAGE_BYTES;

#pragma unroll
        for (int k16 = 0; k16 < 4; k16++) {
            uint32_t afr[2][4];
#pragma unroll
            for (int mt = 0; mt < 2; mt++) {
                const int row = wm * 32 + mt * 16 + (mi & 1) * 8 + r8;
                const int kc = k16 * 2 + (mi >> 1);
                const uint32_t off = (uint32_t)(row * 128 + ((kc ^ (row & 7)) * 16));
                LDSM4(afr[mt], st + off);
            }
            uint32_t bfr[4][4];
#pragma unroll
            for (int nt = 0; nt < 4; nt++) {
                const int row = wn * 64 + nt * 16 + (mi >> 1) * 8 + r8;
                const int kc = k16 * 2 + (mi & 1);
                const uint32_t off = (uint32_t)(row * 128 + ((kc ^ (row & 7)) * 16));
                LDSM4(bfr[nt], st + MAT_BYTES + off);
            }
#pragma unroll
            for (int mt = 0; mt < 2; mt++)
#pragma unroll
                for (int nt = 0; nt < 4; nt++)
#pragma unroll
                    for (int s = 0; s < 2; s++)
                        MMA16816(acc[mt][nt * 2 + s], afr[mt],
                                 bfr[nt][s * 2], bfr[nt][s * 2 + 1]);
        }

        __syncthreads();
        if (cch + 2 < 16) {
            fill_stage(sb + buf * STAGE_BYTES, (cch + 2) * 64, tid, aH, bH);
            CP_WAIT(1);
        } else {
            CP_WAIT(0);
        }
        __syncthreads();
        buf ^= 1;
    }

    // ---- epilogue 1: store C tile as fp16 ----
    __half2* C2 = (__half2*)g_C;
#pragma unroll
    for (int mt = 0; mt < 2; mt++) {
#pragma unroll
        for (int j = 0; j < 8; j++) {
            const int row = row0 + wm * 32 + mt * 16 + (lane >> 2);
            const int col = col0 + wn * 64 + j * 8 + (lane & 3) * 2;
            C2[(size_t)row * (NF / 2) + (col >> 1)] =
                __half2(__float2half_rn(acc[mt][j][0]), __float2half_rn(acc[mt][j][1]));
            C2[(size_t)(row + 8) * (NF / 2) + (col >> 1)] =
                __half2(__float2half_rn(acc[mt][j][2]), __float2half_rn(acc[mt][j][3]));
        }
    }

    // ---- epilogue 2: per-(row, tile) max of fp32 acc (pre-rounding: tight bound) ----
    float (*s_half)[2] = (float (*)[2])smem;    // [128][2], stages are dead now
#pragma unroll
    for (int mt = 0; mt < 2; mt++) {
#pragma unroll
        for (int goff = 0; goff < 2; goff++) {
            float mx = -1e30f;
#pragma unroll
            for (int j = 0; j < 8; j++) {
                mx = fmaxf(mx, acc[mt][j][goff * 2 + 0]);
                mx = fmaxf(mx, acc[mt][j][goff * 2 + 1]);
            }
#pragma unroll
            for (int o = 1; o < 4; o <<= 1)
                mx = fmaxf(mx, __shfl_xor_sync(0xffffffffu, mx, o));
            if ((lane & 3) == 0) {
                const int rl = wm * 32 + mt * 16 + goff * 8 + (lane >> 2);
                s_half[rl][wn] = mx;
            }
        }
    }
    __syncthreads();
    if (tid < 128)
        g_tmax[row0 + tid][bx] = fmaxf(s_half[tid][0], s_half[tid][1]);
}

// ---------------- K3: fused rescue + update (one block of 256 per row) ----------------
#define MAXCAND 128
__global__ __launch_bounds__(256) void k_step(const float* __restrict__ x,
                                              const float* __restrict__ xs) {
    const int b = blockIdx.x;
    const int tid = threadIdx.x;
    const int warp = tid >> 5, lane = tid & 31;

    __shared__ float wr[8];
    __shared__ float s_thr;
    __shared__ int   s_tiles[NTILE];
    __shared__ int   s_nt;
    __shared__ int   s_cand[MAXCAND];
    __shared__ int   s_nc;
    __shared__ unsigned long long s_best;
    __shared__ int   s_idx[L0];
    __shared__ float s_w[L0];
    __shared__ float s_g[L0];
    __shared__ int   s_cnt;
    __shared__ float s_step;
    __shared__ float w_cc[8], w_cr[8], w_nn[8];

    // ---- A1: global max over 256 tile maxes ----
    const float tv = g_tmax[b][tid];
    float mx = tv;
#pragma unroll
    for (int o = 16; o; o >>= 1) mx = fmaxf(mx, __shfl_xor_sync(0xffffffffu, mx, o));
    if (lane == 0) wr[warp] = mx;
    if (tid == 0) { s_nt = 0; s_nc = 0; s_best = 0ull; }
    __syncthreads();
    if (tid == 0) {
        float t = -1e30f;
        for (int i = 0; i < 8; i++) t = fmaxf(t, wr[i]);
        const float Bm = 2.0e-3f * g_rnorm[b] + 1e-7f;
        s_thr = t - 2.f * Bm;
    }
    __syncthreads();
    const float thr = s_thr;

    // ---- A2: flag tiles that can contain the exact argmax ----
    if (tv >= thr) { int p = atomicAdd(&s_nt, 1); s_tiles[p] = tid; }
    __syncthreads();
    const int ntl = s_nt;

    // ---- A3: scan flagged tiles for candidates ----
    const __half2* Crow = (const __half2*)g_C + (size_t)b * (NF / 2);
    for (int tt = 0; tt < ntl; tt++) {
        const int tile = s_tiles[tt];
        if (tid < 64) {
            __half2 v = Crow[tile * 64 + tid];
            float a = __half2float(v.x), c = __half2float(v.y);
            if (a >= thr) { int p = atomicAdd(&s_nc, 1); if (p < MAXCAND) s_cand[p] = tile * 128 + 2 * tid; }
            if (c >= thr) { int p = atomicAdd(&s_nc, 1); if (p < MAXCAND) s_cand[p] = tile * 128 + 2 * tid + 1; }
        }
    }
    __syncthreads();
    const int nc = (s_nc < MAXCAND) ? s_nc : MAXCAND;

    // ---- A4: exact fp32 rescore, one warp per candidate ----
    const float* r = g_res + (size_t)b * ND;
    for (int cdx = warp; cdx < nc; cdx += 8) {
        const int f = s_cand[cdx];
        const float* a = xs + (size_t)f * ND;
        float s = 0.f;
        for (int d = lane; d < ND; d += 32) s = fmaf(r[d], a[d], s);
#pragma unroll
        for (int o = 16; o; o >>= 1) s += __shfl_xor_sync(0xffffffffu, s, o);
        if (lane == 0) atomicMax(&s_best, pack_key(s, f));
    }
    __syncthreads();

    // ---- B: update phase ----
    if (tid == 0) {
        int cnt = g_cnt[b];
        for (int j = 0; j < cnt; j++) { s_idx[j] = g_idx[b * L0 + j]; s_w[j] = g_w[b * L0 + j]; }
        int f = (int)(0xFFFFFFFFu - (unsigned)(s_best & 0xFFFFFFFFull));
        bool present = false;
        for (int j = 0; j < cnt; j++) if (s_idx[j] == f) { present = true; break; }
        if (!present) { s_idx[cnt] = f; s_w[cnt] = 0.f; cnt++; }
        s_cnt = cnt;
    }
    __syncthreads();
    const int m = s_cnt;

    for (int j = warp; j < m; j += 8) {
        const float* a = xs + (size_t)s_idx[j] * ND;
        float s = 0.f;
        for (int d = lane; d < ND; d += 32) s = fmaf(r[d], a[d], s);
#pragma unroll
        for (int o = 16; o; o >>= 1) s += __shfl_xor_sync(0xffffffffu, s, o);
        if (lane == 0) s_g[j] = s;
    }
    __syncthreads();

    float cc = 0.f, cr = 0.f;
    for (int d = tid; d < ND; d += 256) {
        float c = 0.f;
        for (int j = 0; j < m; j++) c = fmaf(s_g[j], xs[(size_t)s_idx[j] * ND + d], c);
        cc = fmaf(c, c, cc);
        cr = fmaf(c, r[d], cr);
    }
#pragma unroll
    for (int o = 16; o; o >>= 1) {
        cc += __shfl_xor_sync(0xffffffffu, cc, o);
        cr += __shfl_xor_sync(0xffffffffu, cr, o);
    }
    if (lane == 0) { w_cc[warp] = cc; w_cr[warp] = cr; }
    __syncthreads();
    if (tid == 0) {
        float tcc = 0.f, tcr = 0.f;
        for (int wv = 0; wv < 8; wv++) { tcc += w_cc[wv]; tcr += w_cr[wv]; }
        s_step = tcr / fmaxf(tcc, EPSF);
    }
    __syncthreads();
    const float step = s_step;

    if (tid == 0) {
        int ncn = 0;
        for (int j = 0; j < m; j++) {
            float wn2 = fmaxf(s_w[j] + step * s_g[j], 0.f);
            if (wn2 > 0.f) { s_idx[ncn] = s_idx[j]; s_w[ncn] = wn2; ncn++; }
        }
        s_cnt = ncn;
        g_cnt[b] = ncn;
        for (int j = 0; j < ncn; j++) { g_idx[b * L0 + j] = s_idx[j]; g_w[b * L0 + j] = s_w[j]; }
    }
    __syncthreads();
    const int mc = s_cnt;

    // rebuild residual (fp32) + fp16 cast + norm for next iteration
    float nn = 0.f;
    for (int d = tid; d < ND; d += 256) {
        float v = x[(size_t)b * ND + d];
        for (int j = 0; j < mc; j++) v = fmaf(-s_w[j], xs[(size_t)s_idx[j] * ND + d], v);
        g_res[(size_t)b * ND + d] = v;
        g_rhi[(size_t)b * ND + d] = __float2half_rn(v);
        nn = fmaf(v, v, nn);
    }
#pragma unroll
    for (int o = 16; o; o >>= 1) nn += __shfl_xor_sync(0xffffffffu, nn, o);
    if (lane == 0) w_nn[warp] = nn;
    __syncthreads();
    if (tid == 0) {
        float t = 0.f;
        for (int wv = 0; wv < 8; wv++) t += w_nn[wv];
        g_rnorm[b] = sqrtf(t);
    }
}

// ---------------- K4: top_k emulation + decode + losses ----------------
__global__ __launch_bounds__(256) void k_finalize(const float* __restrict__ y,
                                                  const float* __restrict__ xs,
                                                  const float* __restrict__ ys,
                                                  float* __restrict__ out) {
    const int b = blockIdx.x;
    const int tid = threadIdx.x;

    __shared__ int   s_idx[L0];
    __shared__ float s_w[L0];
    __shared__ int   s_m;
    __shared__ float wred[8];

    if (tid == 0) {
        int   ti[L0]; float tw[L0];
        int m = g_cnt[b];
        for (int j = 0; j < m; j++) { ti[j] = g_idx[b * L0 + j]; tw[j] = g_w[b * L0 + j]; }
        // stable sort: value desc, index asc on ties (matches jax.lax.top_k)
        for (int i = 1; i < m; i++) {
            float wv = tw[i]; int iv = ti[i]; int j = i - 1;
            while (j >= 0 && (tw[j] < wv || (tw[j] == wv && ti[j] > iv))) {
                tw[j + 1] = tw[j]; ti[j + 1] = ti[j]; j--;
            }
            tw[j + 1] = wv; ti[j + 1] = iv;
        }
        // zero-pad with smallest unused indices (top_k tie rule on zeros)
        int k = m, f = 0;
        while (k < L0) {
            bool used = false;
            for (int j = 0; j < m; j++) if (ti[j] == f) { used = true; break; }
            if (!used) { ti[k] = f; tw[k] = 0.f; k++; }
            f++;
        }
        for (int j = 0; j < L0; j++) { s_idx[j] = ti[j]; s_w[j] = tw[j]; }
        s_m = m;
    }
    __syncthreads();

    float* out_w = out;
    float* out_i = out + (size_t)NB * L0;
    float* out_x = out + (size_t)2 * NB * L0;
    float* out_y = out_x + (size_t)NB * ND;
    float* out_l = out_y + (size_t)NB * ND;

    if (tid < L0) {
        out_w[b * L0 + tid] = s_w[tid];
        out_i[b * L0 + tid] = (float)s_idx[tid];
    }

    const int m = s_m;
    float lsum = 0.f;
    for (int d = tid; d < ND; d += 256) {
        float vx = 0.f, vy = 0.f;
        for (int j = 0; j < m; j++) {
            const float w = s_w[j];
            const size_t f = (size_t)s_idx[j];
            vx = fmaf(w, xs[f * ND + d], vx);
            vy = fmaf(w, ys[f * ND + d], vy);
        }
        out_x[(size_t)b * ND + d] = vx;
        out_y[(size_t)b * ND + d] = vy;
        const float e = vy - y[(size_t)b * ND + d];
        lsum = fmaf(e, e, lsum);
    }
#pragma unroll
    for (int o = 16; o; o >>= 1) lsum += __shfl_xor_sync(0xffffffffu, lsum, o);
    if ((tid & 31) == 0) wred[tid >> 5] = lsum;
    __syncthreads();
    if (tid == 0) {
        float t = 0.f;
        for (int i = 0; i < 8; i++) t += wred[i];
        out_l[b] = t;
    }
}

// ---------------- host launcher ----------------
extern "C" void kernel_launch(void* const* d_in, const int* in_sizes, int n_in,
                              void* d_out, int out_size) {
    const float* x = nullptr; const float* y = nullptr;
    const float* xs = nullptr; const float* ys = nullptr;
    for (int i = 0; i < n_in; i++) {
        if (in_sizes[i] == NB * ND) { if (!x) x = (const float*)d_in[i]; else if (!y) y = (const float*)d_in[i]; }
        else if (in_sizes[i] == NF * ND) { if (!xs) xs = (const float*)d_in[i]; else if (!ys) ys = (const float*)d_in[i]; }
    }
    float* out = (float*)d_out;

    cudaFuncSetAttribute(k_gemm_mma, cudaFuncAttributeMaxDynamicSharedMemorySize, GSMEM);

    {   // one-time fp16 cast of xs (idempotent, deterministic)
        size_t n4 = (size_t)NF * ND / 4;
        k_split_xs<<<(unsigned)((n4 + 255) / 256), 256>>>(xs);
    }
    k_init<<<(NB * ND + 255) / 256, 256>>>(x);
    k_norm0<<<NB, 256>>>();

    const int ngrid = (NF / 128) * (NB / 128);   // 256 * 8 = 2048
    for (int t = 0; t < L0; t++) {
        k_gemm_mma<<<ngrid, 256, GSMEM>>>();
        k_step<<<NB, 256>>>(x, xs);
    }
    k_finalize<<<NB, 256>>>(y, xs, ys, out);
}

// round 7
// speedup vs baseline: 11.0028x; 1.0149x over previous
#include <cuda_runtime.h>
#include <cuda_fp16.h>
#include <stdint.h>

// Problem constants (B, D, F, target_l0) — fixed by the dataset.
#define NB 1024
#define ND 1024
#define NF 32768
#define L0 32
#define EPSF 1e-3f
#define NTILE (NF / 128)        // 256 column tiles

// ---------------- device state (no allocations allowed) ----------------
__device__ float              g_res[NB * ND];            // residual [B,D] fp32
__device__ float              g_rnorm[NB];               // ||r|| per row
__device__ __half             g_rhi[NB * ND];            // residual fp16
__device__ __half             g_xhi[(size_t)NF * ND];    // xs fp16
__device__ __half             g_C[(size_t)NB * NF];      // approx inner products
__device__ float              g_tmax[NB][NTILE];         // per (row, 128-col tile) max
__device__ float              g_w[NB * L0];
__device__ int                g_idx[NB * L0];
__device__ int                g_cnt[NB];

// ---------------- helpers ----------------
__device__ __forceinline__ uint32_t smem_to_u32(const void* p) {
    uint32_t a;
    asm("{ .reg .u64 t; cvta.to.shared.u64 t, %1; cvt.u32.u64 %0, t; }" : "=r"(a) : "l"(p));
    return a;
}

// pack (value, index): larger key == (larger value, then smaller index)
__device__ __forceinline__ unsigned long long pack_key(float v, int idx) {
    unsigned u = __float_as_uint(v);
    u = (u & 0x80000000u) ? ~u : (u | 0x80000000u);
    return ((unsigned long long)u << 32) | (unsigned)(0xFFFFFFFFu - (unsigned)idx);
}

#define LDSM4(f, addr)                                                                 \
    asm volatile("ldmatrix.sync.aligned.m8n8.x4.shared.b16 {%0,%1,%2,%3}, [%4];"       \
                 : "=r"((f)[0]), "=r"((f)[1]), "=r"((f)[2]), "=r"((f)[3]) : "r"(addr))

#define MMA16816(d, a, b0, b1)                                                         \
    asm volatile("mma.sync.aligned.m16n8k16.row.col.f32.f16.f16.f32 "                  \
                 "{%0,%1,%2,%3},{%4,%5,%6,%7},{%8,%9},{%0,%1,%2,%3};"                  \
                 : "+f"((d)[0]), "+f"((d)[1]), "+f"((d)[2]), "+f"((d)[3])              \
                 : "r"((a)[0]), "r"((a)[1]), "r"((a)[2]), "r"((a)[3]),                 \
                   "r"(b0), "r"(b1))

#define CP_ASYNC16(sa, gp) \
    asm volatile("cp.async.cg.shared.global [%0], [%1], 16;" :: "r"(sa), "l"(gp))
#define CP_COMMIT()  asm volatile("cp.async.commit_group;")
#define CP_WAIT(n)   asm volatile("cp.async.wait_group %0;" :: "n"(n))

// ---------------- K-1: one-time fp16 cast of xs ----------------
__global__ void k_split_xs(const float* __restrict__ xs) {
    size_t i = (size_t)blockIdx.x * blockDim.x + threadIdx.x;
    size_t n4 = (size_t)NF * ND / 4;
    if (i >= n4) return;
    float4 v = ((const float4*)xs)[i];
    __half2* ph = (__half2*)g_xhi;
    ph[i * 2 + 0] = __half2(__float2half_rn(v.x), __float2half_rn(v.y));
    ph[i * 2 + 1] = __half2(__float2half_rn(v.z), __float2half_rn(v.w));
}

// ---------------- K0: init ----------------
__global__ void k_init(const float* __restrict__ x) {
    int i = blockIdx.x * blockDim.x + threadIdx.x;
    if (i < NB * ND) {
        float v = x[i];
        g_res[i] = v;
        g_rhi[i] = __float2half_rn(v);
    }
    if (i < NB) g_cnt[i] = 0;
}

// initial residual norms
__global__ __launch_bounds__(256) void k_norm0() {
    const int b = blockIdx.x;
    const int tid = threadIdx.x;
    __shared__ float wr[8];
    float nn = 0.f;
    for (int d = tid; d < ND; d += 256) {
        float v = g_res[(size_t)b * ND + d];
        nn = fmaf(v, v, nn);
    }
#pragma unroll
    for (int o = 16; o; o >>= 1) nn += __shfl_xor_sync(0xffffffffu, nn, o);
    if ((tid & 31) == 0) wr[tid >> 5] = nn;
    __syncthreads();
    if (tid == 0) {
        float t = 0.f;
        for (int i = 0; i < 8; i++) t += wr[i];
        g_rnorm[b] = sqrtf(t);
    }
}

// ---------------- K2: fp16 hi*hi GEMM (mma.sync), store C fp16 + per-tile max ----------------
// CTA tile 128(M) x 128(N), BK=64 (128B fp16 rows, XOR swizzle), 3-stage cp.async ring.
#define MAT_BYTES 16384                 // 128 rows * 128B
#define STAGE_BYTES (2 * MAT_BYTES)     // aH, bH
#define NSTAGE 3
#define GSMEM (NSTAGE * STAGE_BYTES)    // 98304

__device__ __forceinline__ void fill_stage(uint32_t st, int k0, int tid,
                                           const __half* aH, const __half* bH) {
#pragma unroll
    for (int it = 0; it < 8; it++) {
        const int mat = it >> 2;                 // 0 = A, 1 = B
        const int w = (it & 3) * 256 + tid;      // 0..1023 within matrix
        const int row = w >> 3;
        const int c = w & 7;
        const __half* base = mat ? bH : aH;
        const __half* gp = base + (size_t)row * ND + k0 + c * 8;
        uint32_t off = (uint32_t)(row * 128 + ((c ^ (row & 7)) * 16));
        CP_ASYNC16(st + mat * MAT_BYTES + off, gp);
    }
    CP_COMMIT();
}

__global__ __launch_bounds__(256, 2) void k_gemm_mma() {
    extern __shared__ char smem[];
    const uint32_t sb = smem_to_u32(smem);

    const int tid = threadIdx.x;
    const int lane = tid & 31;
    const int wid = tid >> 5;
    const int wm = wid >> 1;      // 0..3 (M)
    const int wn = wid & 1;       // 0..1 (N)
    const int mi = lane >> 3;
    const int r8 = lane & 7;

    const int id = blockIdx.x;
    const int by = id & 7;        // M tiles vary fastest -> CTAs share B tile in L2
    const int bx = id >> 3;
    const int row0 = by * 128;
    const int col0 = bx * 128;

    const __half* aH = g_rhi + (size_t)row0 * ND;
    const __half* bH = g_xhi + (size_t)col0 * ND;

    float acc[2][8][4];
#pragma unroll
    for (int i = 0; i < 2; i++)
#pragma unroll
        for (int j = 0; j < 8; j++)
#pragma unroll
            for (int q = 0; q < 4; q++) acc[i][j][q] = 0.f;

    fill_stage(sb + 0 * STAGE_BYTES, 0, tid, aH, bH);
    fill_stage(sb + 1 * STAGE_BYTES, 64, tid, aH, bH);
    fill_stage(sb + 2 * STAGE_BYTES, 128, tid, aH, bH);

    for (int cch = 0; cch < 16; cch++) {
        const uint32_t st = sb + (cch % NSTAGE) * STAGE_BYTES;
        CP_WAIT(2);               // stage cch's group complete (uniform 1 group/iter)
        __syncthreads();

#pragma unroll
        for (int k16 = 0; k16 < 4; k16++) {
            uint32_t afr[2][4];
#pragma unroll
            for (int mt = 0; mt < 2; mt++) {
                const int row = wm * 32 + mt * 16 + (mi & 1) * 8 + r8;
                const int kc = k16 * 2 + (mi >> 1);
                const uint32_t off = (uint32_t)(row * 128 + ((kc ^ (row & 7)) * 16));
                LDSM4(afr[mt], st + off);
            }
            uint32_t bfr[4][4];
#pragma unroll
            for (int nt = 0; nt < 4; nt++) {
                const int row = wn * 64 + nt * 16 + (mi >> 1) * 8 + r8;
                const int kc = k16 * 2 + (mi & 1);
                const uint32_t off = (uint32_t)(row * 128 + ((kc ^ (row & 7)) * 16));
                LDSM4(bfr[nt], st + MAT_BYTES + off);
            }
#pragma unroll
            for (int mt = 0; mt < 2; mt++)
#pragma unroll
                for (int nt = 0; nt < 4; nt++)
#pragma unroll
                    for (int s = 0; s < 2; s++)
                        MMA16816(acc[mt][nt * 2 + s], afr[mt],
                                 bfr[nt][s * 2], bfr[nt][s * 2 + 1]);
        }

        __syncthreads();          // all warps done reading this stage
        if (cch + NSTAGE < 16)
            fill_stage(st, (cch + NSTAGE) * 64, tid, aH, bH);
        else
            CP_COMMIT();          // empty group keeps wait accounting uniform
    }

    // ---- epilogue 1: store C tile as fp16 ----
    __half2* C2 = (__half2*)g_C;
#pragma unroll
    for (int mt = 0; mt < 2; mt++) {
#pragma unroll
        for (int j = 0; j < 8; j++) {
            const int row = row0 + wm * 32 + mt * 16 + (lane >> 2);
            const int col = col0 + wn * 64 + j * 8 + (lane & 3) * 2;
            C2[(size_t)row * (NF / 2) + (col >> 1)] =
                __half2(__float2half_rn(acc[mt][j][0]), __float2half_rn(acc[mt][j][1]));
            C2[(size_t)(row + 8) * (NF / 2) + (col >> 1)] =
                __half2(__float2half_rn(acc[mt][j][2]), __float2half_rn(acc[mt][j][3]));
        }
    }

    // ---- epilogue 2: per-(row, tile) max of fp32 acc (pre-rounding: tight bound) ----
    CP_WAIT(0);
    __syncthreads();
    float (*s_half)[2] = (float (*)[2])smem;    // stages are dead now
#pragma unroll
    for (int mt = 0; mt < 2; mt++) {
#pragma unroll
        for (int goff = 0; goff < 2; goff++) {
            float mx = -1e30f;
#pragma unroll
            for (int j = 0; j < 8; j++) {
                mx = fmaxf(mx, acc[mt][j][goff * 2 + 0]);
                mx = fmaxf(mx, acc[mt][j][goff * 2 + 1]);
            }
#pragma unroll
            for (int o = 1; o < 4; o <<= 1)
                mx = fmaxf(mx, __shfl_xor_sync(0xffffffffu, mx, o));
            if ((lane & 3) == 0) {
                const int rl = wm * 32 + mt * 16 + goff * 8 + (lane >> 2);
                s_half[rl][wn] = mx;
            }
        }
    }
    __syncthreads();
    if (tid < 128)
        g_tmax[row0 + tid][bx] = fmaxf(s_half[tid][0], s_half[tid][1]);
}

// ---------------- K3: fused rescue + update (one block of 256 per row) ----------------
// Rebuild is algebraic: r_new = (r_old - step*c) + sum_{dropped} wtent_j * xs_j.
#define MAXCAND 128
__global__ __launch_bounds__(256) void k_step(const float* __restrict__ x,
                                              const float* __restrict__ xs) {
    const int b = blockIdx.x;
    const int tid = threadIdx.x;
    const int warp = tid >> 5, lane = tid & 31;

    __shared__ float wr[8];
    __shared__ float s_thr;
    __shared__ int   s_tiles[NTILE];
    __shared__ int   s_nt;
    __shared__ int   s_cand[MAXCAND];
    __shared__ int   s_nc;
    __shared__ unsigned long long s_best;
    __shared__ int   s_idx[L0];
    __shared__ float s_w[L0];
    __shared__ float s_g[L0];
    __shared__ int   s_cnt;
    __shared__ float s_step;
    __shared__ int   s_dropidx[L0];
    __shared__ float s_dropw[L0];
    __shared__ int   s_ndrop;
    __shared__ float s_c[ND];
    __shared__ float w_cc[8], w_cr[8], w_nn[8];

    // ---- A1: global max over 256 tile maxes ----
    const float tv = g_tmax[b][tid];
    float mx = tv;
#pragma unroll
    for (int o = 16; o; o >>= 1) mx = fmaxf(mx, __shfl_xor_sync(0xffffffffu, mx, o));
    if (lane == 0) wr[warp] = mx;
    if (tid == 0) { s_nt = 0; s_nc = 0; s_best = 0ull; s_ndrop = 0; }
    __syncthreads();
    if (tid == 0) {
        float t = -1e30f;
        for (int i = 0; i < 8; i++) t = fmaxf(t, wr[i]);
        const float Bm = 2.0e-3f * g_rnorm[b] + 1e-7f;
        s_thr = t - 2.f * Bm;
    }
    __syncthreads();
    const float thr = s_thr;

    // ---- A2: flag tiles that can contain the exact argmax ----
    if (tv >= thr) { int p = atomicAdd(&s_nt, 1); s_tiles[p] = tid; }
    __syncthreads();
    const int ntl = s_nt;

    // ---- A3: scan flagged tiles for candidates ----
    const __half2* Crow = (const __half2*)g_C + (size_t)b * (NF / 2);
    for (int tt = 0; tt < ntl; tt++) {
        const int tile = s_tiles[tt];
        if (tid < 64) {
            __half2 v = Crow[tile * 64 + tid];
            float a = __half2float(v.x), c = __half2float(v.y);
            if (a >= thr) { int p = atomicAdd(&s_nc, 1); if (p < MAXCAND) s_cand[p] = tile * 128 + 2 * tid; }
            if (c >= thr) { int p = atomicAdd(&s_nc, 1); if (p < MAXCAND) s_cand[p] = tile * 128 + 2 * tid + 1; }
        }
    }
    __syncthreads();
    const int nc = (s_nc < MAXCAND) ? s_nc : MAXCAND;

    // ---- A4: exact fp32 rescore, one warp per candidate ----
    const float* r = g_res + (size_t)b * ND;
    for (int cdx = warp; cdx < nc; cdx += 8) {
        const int f = s_cand[cdx];
        const float* a = xs + (size_t)f * ND;
        float s = 0.f;
        for (int d = lane; d < ND; d += 32) s = fmaf(r[d], a[d], s);
#pragma unroll
        for (int o = 16; o; o >>= 1) s += __shfl_xor_sync(0xffffffffu, s, o);
        if (lane == 0) atomicMax(&s_best, pack_key(s, f));
    }
    __syncthreads();

    // ---- B: build active set ----
    if (tid == 0) {
        int cnt = g_cnt[b];
        for (int j = 0; j < cnt; j++) { s_idx[j] = g_idx[b * L0 + j]; s_w[j] = g_w[b * L0 + j]; }
        int f = (int)(0xFFFFFFFFu - (unsigned)(s_best & 0xFFFFFFFFull));
        bool present = false;
        for (int j = 0; j < cnt; j++) if (s_idx[j] == f) { present = true; break; }
        if (!present) { s_idx[cnt] = f; s_w[cnt] = 0.f; cnt++; }
        s_cnt = cnt;
    }
    __syncthreads();
    const int m = s_cnt;

    // ---- g_j = <r, xs[f_j]> ----
    for (int j = warp; j < m; j += 8) {
        const float* a = xs + (size_t)s_idx[j] * ND;
        float s = 0.f;
        for (int d = lane; d < ND; d += 32) s = fmaf(r[d], a[d], s);
#pragma unroll
        for (int o = 16; o; o >>= 1) s += __shfl_xor_sync(0xffffffffu, s, o);
        if (lane == 0) s_g[j] = s;
    }
    __syncthreads();

    // ---- c[d] = sum_j g_j xs_j[d] (kept in smem); cc, cr ----
    float cc = 0.f, cr = 0.f;
    for (int d = tid; d < ND; d += 256) {
        float c = 0.f;
        for (int j = 0; j < m; j++) c = fmaf(s_g[j], xs[(size_t)s_idx[j] * ND + d], c);
        s_c[d] = c;
        cc = fmaf(c, c, cc);
        cr = fmaf(c, r[d], cr);
    }
#pragma unroll
    for (int o = 16; o; o >>= 1) {
        cc += __shfl_xor_sync(0xffffffffu, cc, o);
        cr += __shfl_xor_sync(0xffffffffu, cr, o);
    }
    if (lane == 0) { w_cc[warp] = cc; w_cr[warp] = cr; }
    __syncthreads();
    if (tid == 0) {
        float tcc = 0.f, tcr = 0.f;
        for (int wv = 0; wv < 8; wv++) { tcc += w_cc[wv]; tcr += w_cr[wv]; }
        s_step = tcr / fmaxf(tcc, EPSF);
    }
    __syncthreads();
    const float step = s_step;

    // ---- relu update + compaction, recording dropped atoms ----
    if (tid == 0) {
        int ncn = 0, nd = 0;
        for (int j = 0; j < m; j++) {
            float wt = s_w[j] + step * s_g[j];
            if (wt > 0.f) { s_idx[ncn] = s_idx[j]; s_w[ncn] = wt; ncn++; }
            else          { s_dropidx[nd] = s_idx[j]; s_dropw[nd] = wt; nd++; }
        }
        s_cnt = ncn;
        s_ndrop = nd;
        g_cnt[b] = ncn;
        for (int j = 0; j < ncn; j++) { g_idx[b * L0 + j] = s_idx[j]; g_w[b * L0 + j] = s_w[j]; }
    }
    __syncthreads();
    const int nd = s_ndrop;

    // ---- algebraic rebuild: r_new = (r_old - step*c) + sum_dropped wtent*xs ----
    float nn = 0.f;
    for (int d = tid; d < ND; d += 256) {
        float v = fmaf(-step, s_c[d], g_res[(size_t)b * ND + d]);
        for (int q = 0; q < nd; q++)
            v = fmaf(s_dropw[q], xs[(size_t)s_dropidx[q] * ND + d], v);
        g_res[(size_t)b * ND + d] = v;
        g_rhi[(size_t)b * ND + d] = __float2half_rn(v);
        nn = fmaf(v, v, nn);
    }
#pragma unroll
    for (int o = 16; o; o >>= 1) nn += __shfl_xor_sync(0xffffffffu, nn, o);
    if (lane == 0) w_nn[warp] = nn;
    __syncthreads();
    if (tid == 0) {
        float t = 0.f;
        for (int wv = 0; wv < 8; wv++) t += w_nn[wv];
        g_rnorm[b] = sqrtf(t);
    }
}

// ---------------- K4: top_k emulation + decode + losses ----------------
__global__ __launch_bounds__(256) void k_finalize(const float* __restrict__ y,
                                                  const float* __restrict__ xs,
                                                  const float* __restrict__ ys,
                                                  float* __restrict__ out) {
    const int b = blockIdx.x;
    const int tid = threadIdx.x;

    __shared__ int   s_idx[L0];
    __shared__ float s_w[L0];
    __shared__ int   s_m;
    __shared__ float wred[8];

    if (tid == 0) {
        int   ti[L0]; float tw[L0];
        int m = g_cnt[b];
        for (int j = 0; j < m; j++) { ti[j] = g_idx[b * L0 + j]; tw[j] = g_w[b * L0 + j]; }
        // stable sort: value desc, index asc on ties (matches jax.lax.top_k)
        for (int i = 1; i < m; i++) {
            float wv = tw[i]; int iv = ti[i]; int j = i - 1;
            while (j >= 0 && (tw[j] < wv || (tw[j] == wv && ti[j] > iv))) {
                tw[j + 1] = tw[j]; ti[j + 1] = ti[j]; j--;
            }
            tw[j + 1] = wv; ti[j + 1] = iv;
        }
        // zero-pad with smallest unused indices (top_k tie rule on zeros)
        int k = m, f = 0;
        while (k < L0) {
            bool used = false;
            for (int j = 0; j < m; j++) if (ti[j] == f) { used = true; break; }
            if (!used) { ti[k] = f; tw[k] = 0.f; k++; }
            f++;
        }
        for (int j = 0; j < L0; j++) { s_idx[j] = ti[j]; s_w[j] = tw[j]; }
        s_m = m;
    }
    __syncthreads();

    float* out_w = out;
    float* out_i = out + (size_t)NB * L0;
    float* out_x = out + (size_t)2 * NB * L0;
    float* out_y = out_x + (size_t)NB * ND;
    float* out_l = out_y + (size_t)NB * ND;

    if (tid < L0) {
        out_w[b * L0 + tid] = s_w[tid];
        out_i[b * L0 + tid] = (float)s_idx[tid];
    }

    const int m = s_m;
    float lsum = 0.f;
    for (int d = tid; d < ND; d += 256) {
        float vx = 0.f, vy = 0.f;
        for (int j = 0; j < m; j++) {
            const float w = s_w[j];
            const size_t f = (size_t)s_idx[j];
            vx = fmaf(w, xs[f * ND + d], vx);
            vy = fmaf(w, ys[f * ND + d], vy);
        }
        out_x[(size_t)b * ND + d] = vx;
        out_y[(size_t)b * ND + d] = vy;
        const float e = vy - y[(size_t)b * ND + d];
        lsum = fmaf(e, e, lsum);
    }
#pragma unroll
    for (int o = 16; o; o >>= 1) lsum += __shfl_xor_sync(0xffffffffu, lsum, o);
    if ((tid & 31) == 0) wred[tid >> 5] = lsum;
    __syncthreads();
    if (tid == 0) {
        float t = 0.f;
        for (int i = 0; i < 8; i++) t += wred[i];
        out_l[b] = t;
    }
}

// ---------------- host launcher ----------------
extern "C" void kernel_launch(void* const* d_in, const int* in_sizes, int n_in,
                              void* d_out, int out_size) {
    const float* x = nullptr; const float* y = nullptr;
    const float* xs = nullptr; const float* ys = nullptr;
    for (int i = 0; i < n_in; i++) {
        if (in_sizes[i] == NB * ND) { if (!x) x = (const float*)d_in[i]; else if (!y) y = (const float*)d_in[i]; }
        else if (in_sizes[i] == NF * ND) { if (!xs) xs = (const float*)d_in[i]; else if (!ys) ys = (const float*)d_in[i]; }
    }
    float* out = (float*)d_out;

    cudaFuncSetAttribute(k_gemm_mma, cudaFuncAttributeMaxDynamicSharedMemorySize, GSMEM);

    {   // one-time fp16 cast of xs (idempotent, deterministic)
        size_t n4 = (size_t)NF * ND / 4;
        k_split_xs<<<(unsigned)((n4 + 255) / 256), 256>>>(xs);
    }
    k_init<<<(NB * ND + 255) / 256, 256>>>(x);
    k_norm0<<<NB, 256>>>();

    const int ngrid = (NF / 128) * (NB / 128);   // 256 * 8 = 2048
    for (int t = 0; t < L0; t++) {
        k_gemm_mma<<<ngrid, 256, GSMEM>>>();
        k_step<<<NB, 256>>>(x, xs);
    }
    k_finalize<<<NB, 256>>>(y, xs, ys, out);
}